// round 8
// baseline (speedup 1.0000x reference)
#include <cuda_runtime.h>
#include <cuda_fp16.h>

#define EMBED 64
#define MAX_NODES 100000
#define MAX_EDGES 1600000
#define SCAN_BLK 1024

// Scratch (zero-initialized at module load; kernels restore zeros each run)
__device__ __half g_h[(size_t)MAX_NODES * EMBED];   // relu(x@W^T+b), fp16
__device__ int    g_hist[MAX_NODES];                // degree per src (zeroed by scan)
__device__ int    g_start[MAX_NODES + 1];           // exclusive scan of hist
__device__ int    g_cursor[MAX_NODES];              // running fill cursor
__device__ int    g_bsum[128];                      // block aggregates (total+1), zeroed by sniff
__device__ int    g_stgt[MAX_EDGES];                // tgt indices sorted by src
__device__ int    g_is64;                           // edge_index dtype flag

#define FMA2(acc, a, b) \
    asm("fma.rn.f32x2 %0, %1, %2, %0;" : "+l"(acc) : "l"(a), "l"(b))

__device__ __forceinline__ unsigned long long pack2(float lo, float hi) {
    unsigned long long r;
    asm("mov.b64 %0, {%1, %2};" : "=l"(r) : "f"(lo), "f"(hi));
    return r;
}
__device__ __forceinline__ float unpack_lo(unsigned long long v) {
    float lo, hi;
    asm("mov.b64 {%0, %1}, %2;" : "=f"(lo), "=f"(hi) : "l"(v));
    return lo;
}
__device__ __forceinline__ float unpack_hi(unsigned long long v) {
    float lo, hi;
    asm("mov.b64 {%0, %1}, %2;" : "=f"(lo), "=f"(hi) : "l"(v));
    return hi;
}

// ---------------------------------------------------------------------------
// Kernel A: sniff edge_index dtype (thread 0) + zero scan aggregates.
// ---------------------------------------------------------------------------
__global__ void sniff_kernel(const unsigned long long* __restrict__ ei) {
    int t = threadIdx.x;
    g_bsum[t] = 0;
    if (t == 0) {
        int ok64 = 1;
        #pragma unroll
        for (int k = 0; k < 8; k++) {
            unsigned long long v = ei[k];
            if ((v >> 32) != 0ull || (v & 0xffffffffull) >= (1u << 28)) ok64 = 0;
        }
        g_is64 = ok64;
    }
}

// ---------------------------------------------------------------------------
// Kernel 1: h = relu(x @ W^T + b), packed fma.rn.f32x2, W via broadcast
// LDS.128, output fp16. Runs on a forked stream.
// ---------------------------------------------------------------------------
__global__ void __launch_bounds__(256) gemm_relu_kernel(
    const float* __restrict__ x,
    const float* __restrict__ W,
    const float* __restrict__ b,
    int n_nodes)
{
    __shared__ float ws[EMBED * EMBED];   // row-major W[o][d]
    __shared__ float bs[EMBED];

    int tid = threadIdx.x;
    const float4* W4 = (const float4*)W;
    #pragma unroll
    for (int i = tid; i < EMBED * EMBED / 4; i += 256)
        ((float4*)ws)[i] = W4[i];
    if (tid < EMBED) bs[tid] = b[tid];
    __syncthreads();

    int n = blockIdx.x * 256 + tid;
    if (n >= n_nodes) return;

    unsigned long long x2[EMBED / 2];
    const float4* xp = (const float4*)(x + (size_t)n * EMBED);
    #pragma unroll
    for (int i = 0; i < 16; i++) {
        float4 v = xp[i];
        x2[2 * i]     = pack2(v.x, v.y);
        x2[2 * i + 1] = pack2(v.z, v.w);
    }

    uint2* hp = (uint2*)(g_h + (size_t)n * EMBED);   // row = 16 uint2
    #pragma unroll 1
    for (int o = 0; o < EMBED; o += 4) {
        unsigned long long a0 = 0ull, a1 = 0ull, a2 = 0ull, a3 = 0ull;
        const ulonglong2* w0 = (const ulonglong2*)(ws + (o + 0) * EMBED);
        const ulonglong2* w1 = (const ulonglong2*)(ws + (o + 1) * EMBED);
        const ulonglong2* w2 = (const ulonglong2*)(ws + (o + 2) * EMBED);
        const ulonglong2* w3 = (const ulonglong2*)(ws + (o + 3) * EMBED);
        #pragma unroll
        for (int d4 = 0; d4 < EMBED / 4; d4++) {
            unsigned long long xa = x2[2 * d4], xb = x2[2 * d4 + 1];
            ulonglong2 q0 = w0[d4];
            ulonglong2 q1 = w1[d4];
            ulonglong2 q2 = w2[d4];
            ulonglong2 q3 = w3[d4];
            FMA2(a0, xa, q0.x); FMA2(a0, xb, q0.y);
            FMA2(a1, xa, q1.x); FMA2(a1, xb, q1.y);
            FMA2(a2, xa, q2.x); FMA2(a2, xb, q2.y);
            FMA2(a3, xa, q3.x); FMA2(a3, xb, q3.y);
        }
        float r0 = fmaxf(bs[o + 0] + unpack_lo(a0) + unpack_hi(a0), 0.f);
        float r1 = fmaxf(bs[o + 1] + unpack_lo(a1) + unpack_hi(a1), 0.f);
        float r2 = fmaxf(bs[o + 2] + unpack_lo(a2) + unpack_hi(a2), 0.f);
        float r3 = fmaxf(bs[o + 3] + unpack_lo(a3) + unpack_hi(a3), 0.f);
        __half2 h01 = __floats2half2_rn(r0, r1);
        __half2 h23 = __floats2half2_rn(r2, r3);
        uint2 st;
        st.x = *(unsigned int*)&h01;
        st.y = *(unsigned int*)&h23;
        hp[o >> 2] = st;
    }
}

// ---------------------------------------------------------------------------
// Kernel 2: histogram of src indices. 4 edges per thread, vector loads.
// ---------------------------------------------------------------------------
__global__ void hist_kernel(const void* __restrict__ ei_raw, int n_edges) {
    int p = blockIdx.x * blockDim.x + threadIdx.x;   // quad index
    int e = p * 4;
    int nq = n_edges >> 2;
    if (p < nq) {
        int s0, s1, s2, s3;
        if (g_is64) {
            ulonglong2 va = ((const ulonglong2*)ei_raw)[2 * p];
            ulonglong2 vb = ((const ulonglong2*)ei_raw)[2 * p + 1];
            s0 = (int)va.x; s1 = (int)va.y; s2 = (int)vb.x; s3 = (int)vb.y;
        } else {
            int4 v = ((const int4*)ei_raw)[p];
            s0 = v.x; s1 = v.y; s2 = v.z; s3 = v.w;
        }
        atomicAdd(&g_hist[s0], 1);
        atomicAdd(&g_hist[s1], 1);
        atomicAdd(&g_hist[s2], 1);
        atomicAdd(&g_hist[s3], 1);
    } else if (p == nq) {
        for (int k = e; k < n_edges; k++) {
            int s = g_is64 ? (int)((const long long*)ei_raw)[k]
                           : ((const int*)ei_raw)[k];
            atomicAdd(&g_hist[s], 1);
        }
    }
}

// ---------------------------------------------------------------------------
// Kernel 3: single-pass exclusive scan of g_hist into g_start (N+1 entries),
// initializing g_cursor and re-zeroing g_hist for the next replay.
// Cross-block prefix via flag-in-value aggregates: g_bsum[bid] = total+1
// (zeroed by sniff); 128 polling threads each wait on one predecessor.
// All blocks (<=98) are co-resident on 148 SMs -> polling is deadlock-free.
// ---------------------------------------------------------------------------
__global__ void __launch_bounds__(SCAN_BLK) scan_kernel(int n_nodes) {
    __shared__ int wsum[32];
    __shared__ int red[128];
    __shared__ int s_off;

    int t = threadIdx.x;
    int bid = blockIdx.x;
    int i = bid * SCAN_BLK + t;
    int v = (i < n_nodes) ? g_hist[i] : 0;
    int lane = t & 31, w = t >> 5;

    // Block-local inclusive scan (warp shuffles).
    int s = v;
    #pragma unroll
    for (int off = 1; off < 32; off <<= 1) {
        int u = __shfl_up_sync(0xffffffffu, s, off);
        if (lane >= off) s += u;
    }
    if (lane == 31) wsum[w] = s;
    __syncthreads();
    if (w == 0) {
        int ws = wsum[lane];
        #pragma unroll
        for (int off = 1; off < 32; off <<= 1) {
            int u = __shfl_up_sync(0xffffffffu, ws, off);
            if (lane >= off) ws += u;
        }
        wsum[lane] = ws;
    }
    __syncthreads();
    int base = (w > 0) ? wsum[w - 1] : 0;
    int incl = base + s;

    // Publish this block's total (flag-in-value: total+1, always nonzero).
    if (t == SCAN_BLK - 1)
        *(volatile int*)&g_bsum[bid] = incl + 1;

    // Gather predecessor totals (threads 0..127 poll one slot each).
    if (t < 128) {
        int val = 0;
        if (t < bid) {
            int g;
            do { g = *(volatile int*)&g_bsum[t]; } while (g == 0);
            val = g - 1;
        }
        red[t] = val;
    }
    __syncthreads();
    if (t < 64) red[t] += red[t + 64];
    __syncthreads();
    if (t < 32) {
        int r = red[t] + red[t + 32];
        #pragma unroll
        for (int off = 16; off > 0; off >>= 1)
            r += __shfl_down_sync(0xffffffffu, r, off);
        if (t == 0) s_off = r;
    }
    __syncthreads();

    int excl = s_off + incl - v;
    if (i <= n_nodes) g_start[i] = excl;     // i==n_nodes slot = grand total
    if (i < n_nodes) {
        g_cursor[i] = excl;
        g_hist[i] = 0;                        // restore invariant for next run
    }
}

// ---------------------------------------------------------------------------
// Kernel 4a: reorder, 4 edges per thread (requires n_edges % 4 == 0).
// ---------------------------------------------------------------------------
__global__ void reorder4_kernel(const void* __restrict__ ei_raw, int n_edges) {
    int p = blockIdx.x * blockDim.x + threadIdx.x;
    if (p * 4 >= n_edges) return;
    int s0, s1, s2, s3, t0, t1, t2, t3;
    if (g_is64) {
        const ulonglong2* ei2 = (const ulonglong2*)ei_raw;
        size_t tb = (size_t)(n_edges >> 1);
        ulonglong2 sa = ei2[2 * p],      sb = ei2[2 * p + 1];
        ulonglong2 ta = ei2[tb + 2 * p], tbv = ei2[tb + 2 * p + 1];
        s0 = (int)sa.x; s1 = (int)sa.y; s2 = (int)sb.x; s3 = (int)sb.y;
        t0 = (int)ta.x; t1 = (int)ta.y; t2 = (int)tbv.x; t3 = (int)tbv.y;
    } else {
        const int4* ei4 = (const int4*)ei_raw;
        size_t tb = (size_t)(n_edges >> 2);
        int4 sv = ei4[p];
        int4 tv = ei4[tb + p];
        s0 = sv.x; s1 = sv.y; s2 = sv.z; s3 = sv.w;
        t0 = tv.x; t1 = tv.y; t2 = tv.z; t3 = tv.w;
    }
    g_stgt[atomicAdd(&g_cursor[s0], 1)] = t0;
    g_stgt[atomicAdd(&g_cursor[s1], 1)] = t1;
    g_stgt[atomicAdd(&g_cursor[s2], 1)] = t2;
    g_stgt[atomicAdd(&g_cursor[s3], 1)] = t3;
}

// Kernel 4b: reorder fallback, 1 edge per thread (any n_edges).
__global__ void reorder1_kernel(const void* __restrict__ ei_raw, int n_edges) {
    int e = blockIdx.x * blockDim.x + threadIdx.x;
    if (e >= n_edges) return;
    int src, tgt;
    if (g_is64) {
        const long long* ei = (const long long*)ei_raw;
        src = (int)ei[e];
        tgt = (int)ei[(size_t)n_edges + e];
    } else {
        const int* ei = (const int*)ei_raw;
        src = ei[e];
        tgt = ei[(size_t)n_edges + e];
    }
    g_stgt[atomicAdd(&g_cursor[src], 1)] = tgt;
}

// ---------------------------------------------------------------------------
// Kernel 5: segmented gather-reduce + mean. 8 lanes per node; lane j owns
// 16 bytes (8 fp16) of the 128B row. Unroll x4. Accumulate fp32, write once.
// Degree = g_start[n+1] - g_start[n].
// ---------------------------------------------------------------------------
__global__ void __launch_bounds__(256) accumulate_kernel(float4* __restrict__ out4,
                                                         int n_nodes)
{
    int t = blockIdx.x * 256 + threadIdx.x;
    int n = t >> 3;
    int j = t & 7;
    if (n >= n_nodes) return;

    int start = g_start[n];
    int deg   = g_start[n + 1] - start;

    const uint4* hp = (const uint4*)g_h;   // row = 8 uint4
    float acc[8] = {0.f, 0.f, 0.f, 0.f, 0.f, 0.f, 0.f, 0.f};

    int k = 0;
    for (; k + 4 <= deg; k += 4) {
        int i0 = __ldg(&g_stgt[start + k]);
        int i1 = __ldg(&g_stgt[start + k + 1]);
        int i2 = __ldg(&g_stgt[start + k + 2]);
        int i3 = __ldg(&g_stgt[start + k + 3]);
        uint4 v0 = hp[(size_t)i0 * 8 + j];
        uint4 v1 = hp[(size_t)i1 * 8 + j];
        uint4 v2 = hp[(size_t)i2 * 8 + j];
        uint4 v3 = hp[(size_t)i3 * 8 + j];
        #pragma unroll
        for (int q = 0; q < 4; q++) {
            unsigned int u0 = (&v0.x)[q];
            unsigned int u1 = (&v1.x)[q];
            unsigned int u2 = (&v2.x)[q];
            unsigned int u3 = (&v3.x)[q];
            float2 f0 = __half22float2(*(__half2*)&u0);
            float2 f1 = __half22float2(*(__half2*)&u1);
            float2 f2 = __half22float2(*(__half2*)&u2);
            float2 f3 = __half22float2(*(__half2*)&u3);
            acc[2 * q]     += (f0.x + f1.x) + (f2.x + f3.x);
            acc[2 * q + 1] += (f0.y + f1.y) + (f2.y + f3.y);
        }
    }
    for (; k < deg; k++) {
        int i0 = __ldg(&g_stgt[start + k]);
        uint4 v0 = hp[(size_t)i0 * 8 + j];
        #pragma unroll
        for (int q = 0; q < 4; q++) {
            unsigned int u0 = (&v0.x)[q];
            float2 f0 = __half22float2(*(__half2*)&u0);
            acc[2 * q]     += f0.x;
            acc[2 * q + 1] += f0.y;
        }
    }

    float inv = 1.0f / fmaxf((float)deg, 1.0f);
    size_t base = (size_t)n * 16 + 2 * j;   // lane j owns floats [8j, 8j+8)
    out4[base]     = make_float4(acc[0] * inv, acc[1] * inv, acc[2] * inv, acc[3] * inv);
    out4[base + 1] = make_float4(acc[4] * inv, acc[5] * inv, acc[6] * inv, acc[7] * inv);
}

// ---------------------------------------------------------------------------
// Launch: gemm forked to a side stream; edge pipeline on main stream; join
// before accumulate.
// ---------------------------------------------------------------------------
extern "C" void kernel_launch(void* const* d_in, const int* in_sizes, int n_in,
                              void* d_out, int out_size)
{
    const float* x  = (const float*)d_in[0];
    const void*  ei = d_in[1];
    const float* W  = (const float*)d_in[2];
    const float* b  = (const float*)d_in[3];
    float*       out = (float*)d_out;

    int N  = in_sizes[0] / EMBED;          // 100000
    int E  = in_sizes[1] / 2;              // 1600000
    int NB = (N + SCAN_BLK - 1) / SCAN_BLK;
    int EQ = E / 4 + 1;                    // edge quads (+1 tail thread)

    cudaStream_t s2;
    cudaEvent_t evFork, evJoin;
    cudaStreamCreateWithFlags(&s2, cudaStreamNonBlocking);
    cudaEventCreateWithFlags(&evFork, cudaEventDisableTiming);
    cudaEventCreateWithFlags(&evJoin, cudaEventDisableTiming);

    // Fork: gemm on side stream.
    cudaEventRecord(evFork, 0);
    cudaStreamWaitEvent(s2, evFork, 0);
    gemm_relu_kernel<<<(N + 255) / 256, 256, 0, s2>>>(x, W, b, N);
    cudaEventRecord(evJoin, s2);

    // Main stream: edge-index pipeline.
    sniff_kernel<<<1, 128>>>((const unsigned long long*)ei);
    hist_kernel<<<(EQ + 255) / 256, 256>>>(ei, E);
    scan_kernel<<<NB, SCAN_BLK>>>(N);
    if ((E & 3) == 0)
        reorder4_kernel<<<(E / 4 + 255) / 256, 256>>>(ei, E);
    else
        reorder1_kernel<<<(E + 255) / 256, 256>>>(ei, E);

    // Join, then accumulate.
    cudaStreamWaitEvent(0, evJoin, 0);
    long long at = (long long)N * 8;
    accumulate_kernel<<<(int)((at + 255) / 256), 256>>>((float4*)out, N);
}

// round 9
// speedup vs baseline: 1.0180x; 1.0180x over previous
#include <cuda_runtime.h>
#include <cuda_fp16.h>

#define EMBED 64
#define MAX_NODES 100000
#define MAX_EDGES 1600000

// Scratch (zero-initialized at module load; accumulate re-zeroes g_head each
// run so graph replays always start from a clean state).
__device__ __half g_h[(size_t)MAX_NODES * EMBED];   // relu(x@W^T+b), fp16
__device__ int    g_head[MAX_NODES];                // list head, 0 = empty, else edge+1
__device__ int2   g_link[MAX_EDGES];                // {next (0=end, else edge+1), tgt}

#define FMA2(acc, a, b) \
    asm("fma.rn.f32x2 %0, %1, %2, %0;" : "+l"(acc) : "l"(a), "l"(b))

__device__ __forceinline__ unsigned long long pack2(float lo, float hi) {
    unsigned long long r;
    asm("mov.b64 %0, {%1, %2};" : "=l"(r) : "f"(lo), "f"(hi));
    return r;
}
__device__ __forceinline__ float unpack_lo(unsigned long long v) {
    float lo, hi;
    asm("mov.b64 {%0, %1}, %2;" : "=f"(lo), "=f"(hi) : "l"(v));
    return lo;
}
__device__ __forceinline__ float unpack_hi(unsigned long long v) {
    float lo, hi;
    asm("mov.b64 {%0, %1}, %2;" : "=f"(lo), "=f"(hi) : "l"(v));
    return hi;
}

// Per-block inline dtype sniff: int64 edge data with node ids < 1e5 has zero
// high halves; int32 data packs two random ids per u64 word.
__device__ __forceinline__ int sniff_is64(const void* ei_raw) {
    const unsigned long long* e8 = (const unsigned long long*)ei_raw;
    int ok64 = 1;
    #pragma unroll
    for (int k = 0; k < 8; k++) {
        unsigned long long v = e8[k];
        if ((v >> 32) != 0ull || (v & 0xffffffffull) >= (1u << 28)) ok64 = 0;
    }
    return ok64;
}

// ---------------------------------------------------------------------------
// Kernel 1: h = relu(x @ W^T + b), packed fma.rn.f32x2, W via broadcast
// LDS.128, output fp16. Runs on a forked stream.
// ---------------------------------------------------------------------------
__global__ void __launch_bounds__(256) gemm_relu_kernel(
    const float* __restrict__ x,
    const float* __restrict__ W,
    const float* __restrict__ b,
    int n_nodes)
{
    __shared__ float ws[EMBED * EMBED];   // row-major W[o][d]
    __shared__ float bs[EMBED];

    int tid = threadIdx.x;
    const float4* W4 = (const float4*)W;
    #pragma unroll
    for (int i = tid; i < EMBED * EMBED / 4; i += 256)
        ((float4*)ws)[i] = W4[i];
    if (tid < EMBED) bs[tid] = b[tid];
    __syncthreads();

    int n = blockIdx.x * 256 + tid;
    if (n >= n_nodes) return;

    unsigned long long x2[EMBED / 2];
    const float4* xp = (const float4*)(x + (size_t)n * EMBED);
    #pragma unroll
    for (int i = 0; i < 16; i++) {
        float4 v = xp[i];
        x2[2 * i]     = pack2(v.x, v.y);
        x2[2 * i + 1] = pack2(v.z, v.w);
    }

    uint2* hp = (uint2*)(g_h + (size_t)n * EMBED);   // row = 16 uint2
    #pragma unroll 1
    for (int o = 0; o < EMBED; o += 4) {
        unsigned long long a0 = 0ull, a1 = 0ull, a2 = 0ull, a3 = 0ull;
        const ulonglong2* w0 = (const ulonglong2*)(ws + (o + 0) * EMBED);
        const ulonglong2* w1 = (const ulonglong2*)(ws + (o + 1) * EMBED);
        const ulonglong2* w2 = (const ulonglong2*)(ws + (o + 2) * EMBED);
        const ulonglong2* w3 = (const ulonglong2*)(ws + (o + 3) * EMBED);
        #pragma unroll
        for (int d4 = 0; d4 < EMBED / 4; d4++) {
            unsigned long long xa = x2[2 * d4], xb = x2[2 * d4 + 1];
            ulonglong2 q0 = w0[d4];
            ulonglong2 q1 = w1[d4];
            ulonglong2 q2 = w2[d4];
            ulonglong2 q3 = w3[d4];
            FMA2(a0, xa, q0.x); FMA2(a0, xb, q0.y);
            FMA2(a1, xa, q1.x); FMA2(a1, xb, q1.y);
            FMA2(a2, xa, q2.x); FMA2(a2, xb, q2.y);
            FMA2(a3, xa, q3.x); FMA2(a3, xb, q3.y);
        }
        float r0 = fmaxf(bs[o + 0] + unpack_lo(a0) + unpack_hi(a0), 0.f);
        float r1 = fmaxf(bs[o + 1] + unpack_lo(a1) + unpack_hi(a1), 0.f);
        float r2 = fmaxf(bs[o + 2] + unpack_lo(a2) + unpack_hi(a2), 0.f);
        float r3 = fmaxf(bs[o + 3] + unpack_lo(a3) + unpack_hi(a3), 0.f);
        __half2 h01 = __floats2half2_rn(r0, r1);
        __half2 h23 = __floats2half2_rn(r2, r3);
        uint2 st;
        st.x = *(unsigned int*)&h01;
        st.y = *(unsigned int*)&h23;
        hp[o >> 2] = st;
    }
}

// ---------------------------------------------------------------------------
// Kernel 2: chain build. For each edge e: push e onto src's linked list and
// record {next, tgt} at g_link[e] (coalesced store). 4 edges per thread.
// ---------------------------------------------------------------------------
__global__ void __launch_bounds__(256) chain_kernel(const void* __restrict__ ei_raw,
                                                    int n_edges)
{
    __shared__ int s_is64;
    if (threadIdx.x == 0) s_is64 = sniff_is64(ei_raw);
    __syncthreads();
    int is64 = s_is64;

    int p = blockIdx.x * 256 + threadIdx.x;   // quad index
    int nq = n_edges >> 2;
    if (p < nq) {
        int e = p * 4;
        int s0, s1, s2, s3, t0, t1, t2, t3;
        if (is64) {
            const ulonglong2* ei2 = (const ulonglong2*)ei_raw;
            size_t tb = (size_t)(n_edges >> 1);
            ulonglong2 sa = ei2[2 * p],      sb  = ei2[2 * p + 1];
            ulonglong2 ta = ei2[tb + 2 * p], tbv = ei2[tb + 2 * p + 1];
            s0 = (int)sa.x; s1 = (int)sa.y; s2 = (int)sb.x; s3 = (int)sb.y;
            t0 = (int)ta.x; t1 = (int)ta.y; t2 = (int)tbv.x; t3 = (int)tbv.y;
        } else {
            const int4* ei4 = (const int4*)ei_raw;
            size_t tb = (size_t)(n_edges >> 2);
            int4 sv = ei4[p];
            int4 tv = ei4[tb + p];
            s0 = sv.x; s1 = sv.y; s2 = sv.z; s3 = sv.w;
            t0 = tv.x; t1 = tv.y; t2 = tv.z; t3 = tv.w;
        }
        int o0 = atomicExch(&g_head[s0], e + 1);
        int o1 = atomicExch(&g_head[s1], e + 2);
        int o2 = atomicExch(&g_head[s2], e + 3);
        int o3 = atomicExch(&g_head[s3], e + 4);
        g_link[e]     = make_int2(o0, t0);
        g_link[e + 1] = make_int2(o1, t1);
        g_link[e + 2] = make_int2(o2, t2);
        g_link[e + 3] = make_int2(o3, t3);
    } else if (p == nq) {
        for (int e = p * 4; e < n_edges; e++) {
            int src, tgt;
            if (is64) {
                const long long* ei = (const long long*)ei_raw;
                src = (int)ei[e];
                tgt = (int)ei[(size_t)n_edges + e];
            } else {
                const int* ei = (const int*)ei_raw;
                src = ei[e];
                tgt = ei[(size_t)n_edges + e];
            }
            int o = atomicExch(&g_head[src], e + 1);
            g_link[e] = make_int2(o, tgt);
        }
    }
}

// ---------------------------------------------------------------------------
// Kernel 3: chain-walk gather-reduce + mean. 8 lanes per node; lane j owns
// 16B (8 fp16) of the 128B row. All lanes chase the same list (broadcast 8B
// link loads); row gathers are coalesced 128B lines. Accumulate fp32, write
// once. Resets g_head[n]=0 for the next graph replay.
// ---------------------------------------------------------------------------
__global__ void __launch_bounds__(256) accumulate_kernel(float4* __restrict__ out4,
                                                         int n_nodes)
{
    int t = blockIdx.x * 256 + threadIdx.x;
    int n = t >> 3;
    int j = t & 7;
    if (n >= n_nodes) return;

    int e1 = g_head[n];

    const uint4* hp = (const uint4*)g_h;   // row = 8 uint4
    float acc[8] = {0.f, 0.f, 0.f, 0.f, 0.f, 0.f, 0.f, 0.f};
    int deg = 0;

    while (e1) {
        int2 ln = __ldg(&g_link[e1 - 1]);
        uint4 v = hp[(size_t)ln.y * 8 + j];
        e1 = ln.x;
        deg++;
        #pragma unroll
        for (int q = 0; q < 4; q++) {
            unsigned int u = (&v.x)[q];
            float2 f = __half22float2(*(__half2*)&u);
            acc[2 * q]     += f.x;
            acc[2 * q + 1] += f.y;
        }
    }

    if (j == 0) g_head[n] = 0;   // restore invariant for next replay

    float inv = 1.0f / fmaxf((float)deg, 1.0f);
    size_t base = (size_t)n * 16 + 2 * j;   // lane j owns floats [8j, 8j+8)
    out4[base]     = make_float4(acc[0] * inv, acc[1] * inv, acc[2] * inv, acc[3] * inv);
    out4[base + 1] = make_float4(acc[4] * inv, acc[5] * inv, acc[6] * inv, acc[7] * inv);
}

// ---------------------------------------------------------------------------
// Launch: gemm forked to a side stream; chain build on main stream; join
// before the chain-walk accumulate.
// ---------------------------------------------------------------------------
extern "C" void kernel_launch(void* const* d_in, const int* in_sizes, int n_in,
                              void* d_out, int out_size)
{
    const float* x  = (const float*)d_in[0];
    const void*  ei = d_in[1];
    const float* W  = (const float*)d_in[2];
    const float* b  = (const float*)d_in[3];
    float*       out = (float*)d_out;

    int N  = in_sizes[0] / EMBED;          // 100000
    int E  = in_sizes[1] / 2;              // 1600000
    int EQ = E / 4 + 1;                    // edge quads (+1 tail thread)

    cudaStream_t s2;
    cudaEvent_t evFork, evJoin;
    cudaStreamCreateWithFlags(&s2, cudaStreamNonBlocking);
    cudaEventCreateWithFlags(&evFork, cudaEventDisableTiming);
    cudaEventCreateWithFlags(&evJoin, cudaEventDisableTiming);

    // Fork: gemm on side stream.
    cudaEventRecord(evFork, 0);
    cudaStreamWaitEvent(s2, evFork, 0);
    gemm_relu_kernel<<<(N + 255) / 256, 256, 0, s2>>>(x, W, b, N);
    cudaEventRecord(evJoin, s2);

    // Main stream: build per-src linked lists.
    chain_kernel<<<(EQ + 255) / 256, 256>>>(ei, E);

    // Join, then walk the chains.
    cudaStreamWaitEvent(0, evJoin, 0);
    long long at = (long long)N * 8;
    accumulate_kernel<<<(int)((at + 255) / 256), 256>>>((float4*)out, N);
}

// round 10
// speedup vs baseline: 1.0606x; 1.0418x over previous
#include <cuda_runtime.h>
#include <cuda_fp16.h>

#define EMBED 64
#define MAX_NODES 100000
#define MAX_EDGES 1600000

// Scratch (zero-initialized at module load; accumulate re-zeroes g_head each
// run so graph replays always start from a clean state).
__device__ __half g_h[(size_t)MAX_NODES * EMBED];   // relu(x@W^T+b), fp16
__device__ int    g_head[MAX_NODES];                // list head, 0 = empty, else edge+1
__device__ int2   g_link[MAX_EDGES];                // {next (0=end, else edge+1), tgt}

__device__ __forceinline__ unsigned int f2tf32(float v) {
    unsigned int r;
    asm("cvt.rna.tf32.f32 %0, %1;" : "=r"(r) : "f"(v));
    return r;
}

// Per-block inline dtype sniff: int64 edge data with node ids < 1e5 has zero
// high halves; int32 data packs two random ids per u64 word.
__device__ __forceinline__ int sniff_is64(const void* ei_raw) {
    const unsigned long long* e8 = (const unsigned long long*)ei_raw;
    int ok64 = 1;
    #pragma unroll
    for (int k = 0; k < 8; k++) {
        unsigned long long v = e8[k];
        if ((v >> 32) != 0ull || (v & 0xffffffffull) >= (1u << 28)) ok64 = 0;
    }
    return ok64;
}

// ---------------------------------------------------------------------------
// Kernel 1: h = relu(x @ W^T + b) via mma.sync.m16n8k8.tf32 (tensor pipe).
// One warp computes a 16-node x 64-output tile: 8 k-tiles x 8 n-tiles = 64 MMA.
// A fragments loaded directly from global x (each element once, L1-friendly);
// W converted to tf32 once per block into smem; epilogue fuses bias + ReLU +
// fp16 pack. Runs on a forked stream.
// ---------------------------------------------------------------------------
__global__ void __launch_bounds__(256) gemm_relu_kernel(
    const float* __restrict__ x,
    const float* __restrict__ W,
    const float* __restrict__ b,
    int n_nodes)
{
    __shared__ unsigned int ws[EMBED * EMBED];  // W[o][k] as tf32 bits
    __shared__ float bs[EMBED];

    int tid = threadIdx.x;
    for (int i = tid; i < EMBED * EMBED; i += 256)
        ws[i] = f2tf32(W[i]);
    if (tid < EMBED) bs[tid] = b[tid];
    __syncthreads();

    int warp = (blockIdx.x * 256 + tid) >> 5;
    int lane = tid & 31;
    int m0 = warp * 16;
    if (m0 >= n_nodes) return;

    int g   = lane >> 2;   // group 0..7
    int tig = lane & 3;    // 0..3

    int row0 = m0 + g;
    int row8 = m0 + g + 8;
    int r0c = (row0 < n_nodes) ? row0 : (n_nodes - 1);  // clamp for tails
    int r8c = (row8 < n_nodes) ? row8 : (n_nodes - 1);
    const float* xr0 = x + (size_t)r0c * EMBED;
    const float* xr8 = x + (size_t)r8c * EMBED;

    float c[8][4];
    #pragma unroll
    for (int nt = 0; nt < 8; nt++)
        c[nt][0] = c[nt][1] = c[nt][2] = c[nt][3] = 0.f;

    #pragma unroll
    for (int kt = 0; kt < 8; kt++) {
        int k0 = kt * 8;
        // A fragment (m16k8): a0=(g,tig) a1=(g+8,tig) a2=(g,tig+4) a3=(g+8,tig+4)
        unsigned int a0 = f2tf32(__ldg(xr0 + k0 + tig));
        unsigned int a1 = f2tf32(__ldg(xr8 + k0 + tig));
        unsigned int a2 = f2tf32(__ldg(xr0 + k0 + tig + 4));
        unsigned int a3 = f2tf32(__ldg(xr8 + k0 + tig + 4));
        #pragma unroll
        for (int nt = 0; nt < 8; nt++) {
            // B fragment (k8n8, col-major): b0=(k=tig, n=g) b1=(k=tig+4, n=g)
            // B[k][n] = W[n][k] with n = nt*8 + g
            unsigned int b0 = ws[(nt * 8 + g) * EMBED + k0 + tig];
            unsigned int b1 = ws[(nt * 8 + g) * EMBED + k0 + tig + 4];
            asm volatile(
                "mma.sync.aligned.m16n8k8.row.col.f32.tf32.tf32.f32 "
                "{%0,%1,%2,%3}, {%4,%5,%6,%7}, {%8,%9}, {%0,%1,%2,%3};"
                : "+f"(c[nt][0]), "+f"(c[nt][1]), "+f"(c[nt][2]), "+f"(c[nt][3])
                : "r"(a0), "r"(a1), "r"(a2), "r"(a3), "r"(b0), "r"(b1));
        }
    }

    // Epilogue: bias + relu + fp16 pack. c[nt] = {(g,2t),(g,2t+1),(g+8,2t),(g+8,2t+1)}
    unsigned int* hp = (unsigned int*)g_h;  // 2 halves per u32
    #pragma unroll
    for (int nt = 0; nt < 8; nt++) {
        int col = nt * 8 + 2 * tig;
        float b0v = bs[col], b1v = bs[col + 1];
        float v00 = fmaxf(c[nt][0] + b0v, 0.f);
        float v01 = fmaxf(c[nt][1] + b1v, 0.f);
        float v10 = fmaxf(c[nt][2] + b0v, 0.f);
        float v11 = fmaxf(c[nt][3] + b1v, 0.f);
        __half2 h0 = __floats2half2_rn(v00, v01);
        __half2 h1 = __floats2half2_rn(v10, v11);
        if (row0 < n_nodes)
            hp[((size_t)row0 * EMBED + col) >> 1] = *(unsigned int*)&h0;
        if (row8 < n_nodes)
            hp[((size_t)row8 * EMBED + col) >> 1] = *(unsigned int*)&h1;
    }
}

// ---------------------------------------------------------------------------
// Kernel 2: chain build. For each edge e: push e onto src's linked list and
// record {next, tgt} at g_link[e] (coalesced store). 4 edges per thread.
// ---------------------------------------------------------------------------
__global__ void __launch_bounds__(256) chain_kernel(const void* __restrict__ ei_raw,
                                                    int n_edges)
{
    __shared__ int s_is64;
    if (threadIdx.x == 0) s_is64 = sniff_is64(ei_raw);
    __syncthreads();
    int is64 = s_is64;

    int p = blockIdx.x * 256 + threadIdx.x;   // quad index
    int nq = n_edges >> 2;
    if (p < nq) {
        int e = p * 4;
        int s0, s1, s2, s3, t0, t1, t2, t3;
        if (is64) {
            const ulonglong2* ei2 = (const ulonglong2*)ei_raw;
            size_t tb = (size_t)(n_edges >> 1);
            ulonglong2 sa = ei2[2 * p],      sb  = ei2[2 * p + 1];
            ulonglong2 ta = ei2[tb + 2 * p], tbv = ei2[tb + 2 * p + 1];
            s0 = (int)sa.x; s1 = (int)sa.y; s2 = (int)sb.x; s3 = (int)sb.y;
            t0 = (int)ta.x; t1 = (int)ta.y; t2 = (int)tbv.x; t3 = (int)tbv.y;
        } else {
            const int4* ei4 = (const int4*)ei_raw;
            size_t tb = (size_t)(n_edges >> 2);
            int4 sv = ei4[p];
            int4 tv = ei4[tb + p];
            s0 = sv.x; s1 = sv.y; s2 = sv.z; s3 = sv.w;
            t0 = tv.x; t1 = tv.y; t2 = tv.z; t3 = tv.w;
        }
        int o0 = atomicExch(&g_head[s0], e + 1);
        int o1 = atomicExch(&g_head[s1], e + 2);
        int o2 = atomicExch(&g_head[s2], e + 3);
        int o3 = atomicExch(&g_head[s3], e + 4);
        g_link[e]     = make_int2(o0, t0);
        g_link[e + 1] = make_int2(o1, t1);
        g_link[e + 2] = make_int2(o2, t2);
        g_link[e + 3] = make_int2(o3, t3);
    } else if (p == nq) {
        for (int e = p * 4; e < n_edges; e++) {
            int src, tgt;
            if (is64) {
                const long long* ei = (const long long*)ei_raw;
                src = (int)ei[e];
                tgt = (int)ei[(size_t)n_edges + e];
            } else {
                const int* ei = (const int*)ei_raw;
                src = ei[e];
                tgt = ei[(size_t)n_edges + e];
            }
            int o = atomicExch(&g_head[src], e + 1);
            g_link[e] = make_int2(o, tgt);
        }
    }
}

// ---------------------------------------------------------------------------
// Kernel 3: chain-walk gather-reduce + mean. 8 lanes per node; lane j owns
// 16B (8 fp16) of the 128B row. All lanes chase the same list (broadcast 8B
// link loads); row gathers are coalesced 128B lines. Accumulate fp32, write
// once. Resets g_head[n]=0 for the next graph replay.
// ---------------------------------------------------------------------------
__global__ void __launch_bounds__(256) accumulate_kernel(float4* __restrict__ out4,
                                                         int n_nodes)
{
    int t = blockIdx.x * 256 + threadIdx.x;
    int n = t >> 3;
    int j = t & 7;
    if (n >= n_nodes) return;

    int e1 = g_head[n];

    const uint4* hp = (const uint4*)g_h;   // row = 8 uint4
    float acc[8] = {0.f, 0.f, 0.f, 0.f, 0.f, 0.f, 0.f, 0.f};
    int deg = 0;

    while (e1) {
        int2 ln = __ldg(&g_link[e1 - 1]);
        uint4 v = hp[(size_t)ln.y * 8 + j];
        e1 = ln.x;
        deg++;
        #pragma unroll
        for (int q = 0; q < 4; q++) {
            unsigned int u = (&v.x)[q];
            float2 f = __half22float2(*(__half2*)&u);
            acc[2 * q]     += f.x;
            acc[2 * q + 1] += f.y;
        }
    }

    if (j == 0) g_head[n] = 0;   // restore invariant for next replay

    float inv = 1.0f / fmaxf((float)deg, 1.0f);
    size_t base = (size_t)n * 16 + 2 * j;   // lane j owns floats [8j, 8j+8)
    out4[base]     = make_float4(acc[0] * inv, acc[1] * inv, acc[2] * inv, acc[3] * inv);
    out4[base + 1] = make_float4(acc[4] * inv, acc[5] * inv, acc[6] * inv, acc[7] * inv);
}

// ---------------------------------------------------------------------------
// Launch: gemm forked to a side stream; chain build on main stream; join
// before the chain-walk accumulate.
// ---------------------------------------------------------------------------
extern "C" void kernel_launch(void* const* d_in, const int* in_sizes, int n_in,
                              void* d_out, int out_size)
{
    const float* x  = (const float*)d_in[0];
    const void*  ei = d_in[1];
    const float* W  = (const float*)d_in[2];
    const float* b  = (const float*)d_in[3];
    float*       out = (float*)d_out;

    int N  = in_sizes[0] / EMBED;          // 100000
    int E  = in_sizes[1] / 2;              // 1600000
    int EQ = E / 4 + 1;                    // edge quads (+1 tail thread)
    int GB = (N + 127) / 128;              // gemm blocks (8 warps x 16 nodes)

    cudaStream_t s2;
    cudaEvent_t evFork, evJoin;
    cudaStreamCreateWithFlags(&s2, cudaStreamNonBlocking);
    cudaEventCreateWithFlags(&evFork, cudaEventDisableTiming);
    cudaEventCreateWithFlags(&evJoin, cudaEventDisableTiming);

    // Fork: gemm on side stream.
    cudaEventRecord(evFork, 0);
    cudaStreamWaitEvent(s2, evFork, 0);
    gemm_relu_kernel<<<GB, 256, 0, s2>>>(x, W, b, N);
    cudaEventRecord(evJoin, s2);

    // Main stream: build per-src linked lists.
    chain_kernel<<<(EQ + 255) / 256, 256>>>(ei, E);

    // Join, then walk the chains.
    cudaStreamWaitEvent(0, evJoin, 0);
    long long at = (long long)N * 8;
    accumulate_kernel<<<(int)((at + 255) / 256), 256>>>((float4*)out, N);
}

// round 11
// speedup vs baseline: 1.1754x; 1.1083x over previous
#include <cuda_runtime.h>
#include <cuda_fp16.h>

#define EMBED 64
#define MAX_NODES 100000
#define MAX_EDGES 1600000
#define WSTRIDE 68   // smem row stride (words) -> conflict-free B-fragment loads

// Scratch (zero-initialized at module load; accumulate re-zeroes g_head each
// run so graph replays always start from a clean state).
__device__ __half g_h[(size_t)MAX_NODES * EMBED];   // relu(x@W^T+b), fp16
__device__ int    g_head[MAX_NODES];                // list head, 0 = empty, else edge+1
__device__ int2   g_link[MAX_EDGES];                // {next (0=end, else edge+1), tgt}

__device__ __forceinline__ unsigned int f2tf32(float v) {
    unsigned int r;
    asm("cvt.rna.tf32.f32 %0, %1;" : "=r"(r) : "f"(v));
    return r;
}

// Per-block inline dtype sniff: int64 edge data with node ids < 1e5 has zero
// high halves; int32 data packs two random ids per u64 word.
__device__ __forceinline__ int sniff_is64(const void* ei_raw) {
    const unsigned long long* e8 = (const unsigned long long*)ei_raw;
    int ok64 = 1;
    #pragma unroll
    for (int k = 0; k < 8; k++) {
        unsigned long long v = e8[k];
        if ((v >> 32) != 0ull || (v & 0xffffffffull) >= (1u << 28)) ok64 = 0;
    }
    return ok64;
}

// ---------------------------------------------------------------------------
// Kernel 1: h = relu(x @ W^T + b) via mma.sync.m16n8k8.tf32.
// One warp computes a 32-node x 64-output tile as TWO m16 tiles sharing each
// B fragment (1 LDS per MMA). W staged in smem with stride 68 words so the
// B-fragment access pattern (4g + tig) is a perfect bank permutation.
// Epilogue fuses bias + ReLU + fp16 pack. Runs on a forked stream.
// ---------------------------------------------------------------------------
__global__ void __launch_bounds__(256) gemm_relu_kernel(
    const float* __restrict__ x,
    const float* __restrict__ W,
    const float* __restrict__ b,
    int n_nodes)
{
    __shared__ unsigned int ws[EMBED * WSTRIDE];  // W[o][k] tf32, padded rows
    __shared__ float bs[EMBED];

    int tid = threadIdx.x;
    for (int i = tid; i < EMBED * EMBED; i += 256) {
        int o = i >> 6, k = i & 63;
        ws[o * WSTRIDE + k] = f2tf32(W[i]);
    }
    if (tid < EMBED) bs[tid] = b[tid];
    __syncthreads();

    int warp = (blockIdx.x * 256 + tid) >> 5;
    int lane = tid & 31;
    int m0 = warp * 32;
    if (m0 >= n_nodes) return;

    int g   = lane >> 2;   // group 0..7
    int tig = lane & 3;    // 0..3

    // Two m16 tiles: rows m0+g / m0+g+8  and  m0+16+g / m0+24+g (clamped).
    int rowA0 = m0 + g,      rowA8 = m0 + g + 8;
    int rowB0 = m0 + 16 + g, rowB8 = m0 + 24 + g;
    int cA0 = (rowA0 < n_nodes) ? rowA0 : (n_nodes - 1);
    int cA8 = (rowA8 < n_nodes) ? rowA8 : (n_nodes - 1);
    int cB0 = (rowB0 < n_nodes) ? rowB0 : (n_nodes - 1);
    int cB8 = (rowB8 < n_nodes) ? rowB8 : (n_nodes - 1);
    const float* xA0 = x + (size_t)cA0 * EMBED;
    const float* xA8 = x + (size_t)cA8 * EMBED;
    const float* xB0 = x + (size_t)cB0 * EMBED;
    const float* xB8 = x + (size_t)cB8 * EMBED;

    float cA[8][4], cB[8][4];
    #pragma unroll
    for (int nt = 0; nt < 8; nt++) {
        cA[nt][0] = cA[nt][1] = cA[nt][2] = cA[nt][3] = 0.f;
        cB[nt][0] = cB[nt][1] = cB[nt][2] = cB[nt][3] = 0.f;
    }

    #pragma unroll
    for (int kt = 0; kt < 8; kt++) {
        int k0 = kt * 8;
        // A fragments (m16k8): a0=(g,tig) a1=(g+8,tig) a2=(g,tig+4) a3=(g+8,tig+4)
        unsigned int aA0 = f2tf32(__ldg(xA0 + k0 + tig));
        unsigned int aA1 = f2tf32(__ldg(xA8 + k0 + tig));
        unsigned int aA2 = f2tf32(__ldg(xA0 + k0 + tig + 4));
        unsigned int aA3 = f2tf32(__ldg(xA8 + k0 + tig + 4));
        unsigned int aB0 = f2tf32(__ldg(xB0 + k0 + tig));
        unsigned int aB1 = f2tf32(__ldg(xB8 + k0 + tig));
        unsigned int aB2 = f2tf32(__ldg(xB0 + k0 + tig + 4));
        unsigned int aB3 = f2tf32(__ldg(xB8 + k0 + tig + 4));
        #pragma unroll
        for (int nt = 0; nt < 8; nt++) {
            // B fragment (k8n8 col-major): B[k][n] = W[n][k], n = nt*8+g
            const unsigned int* wrow = ws + (nt * 8 + g) * WSTRIDE + k0 + tig;
            unsigned int b0 = wrow[0];
            unsigned int b1 = wrow[4];
            asm volatile(
                "mma.sync.aligned.m16n8k8.row.col.f32.tf32.tf32.f32 "
                "{%0,%1,%2,%3}, {%4,%5,%6,%7}, {%8,%9}, {%0,%1,%2,%3};"
                : "+f"(cA[nt][0]), "+f"(cA[nt][1]), "+f"(cA[nt][2]), "+f"(cA[nt][3])
                : "r"(aA0), "r"(aA1), "r"(aA2), "r"(aA3), "r"(b0), "r"(b1));
            asm volatile(
                "mma.sync.aligned.m16n8k8.row.col.f32.tf32.tf32.f32 "
                "{%0,%1,%2,%3}, {%4,%5,%6,%7}, {%8,%9}, {%0,%1,%2,%3};"
                : "+f"(cB[nt][0]), "+f"(cB[nt][1]), "+f"(cB[nt][2]), "+f"(cB[nt][3])
                : "r"(aB0), "r"(aB1), "r"(aB2), "r"(aB3), "r"(b0), "r"(b1));
        }
    }

    // Epilogue: bias + relu + fp16 pack. c[nt] = {(g,2t),(g,2t+1),(g+8,2t),(g+8,2t+1)}
    unsigned int* hp = (unsigned int*)g_h;  // 2 halves per u32
    #pragma unroll
    for (int nt = 0; nt < 8; nt++) {
        int col = nt * 8 + 2 * tig;
        float b0v = bs[col], b1v = bs[col + 1];
        __half2 h00 = __floats2half2_rn(fmaxf(cA[nt][0] + b0v, 0.f),
                                        fmaxf(cA[nt][1] + b1v, 0.f));
        __half2 h08 = __floats2half2_rn(fmaxf(cA[nt][2] + b0v, 0.f),
                                        fmaxf(cA[nt][3] + b1v, 0.f));
        __half2 h10 = __floats2half2_rn(fmaxf(cB[nt][0] + b0v, 0.f),
                                        fmaxf(cB[nt][1] + b1v, 0.f));
        __half2 h18 = __floats2half2_rn(fmaxf(cB[nt][2] + b0v, 0.f),
                                        fmaxf(cB[nt][3] + b1v, 0.f));
        if (rowA0 < n_nodes) hp[((size_t)rowA0 * EMBED + col) >> 1] = *(unsigned int*)&h00;
        if (rowA8 < n_nodes) hp[((size_t)rowA8 * EMBED + col) >> 1] = *(unsigned int*)&h08;
        if (rowB0 < n_nodes) hp[((size_t)rowB0 * EMBED + col) >> 1] = *(unsigned int*)&h10;
        if (rowB8 < n_nodes) hp[((size_t)rowB8 * EMBED + col) >> 1] = *(unsigned int*)&h18;
    }
}

// ---------------------------------------------------------------------------
// Kernel 2: chain build. For each edge e: push e onto src's linked list and
// record {next, tgt} at g_link[e] (coalesced store). 4 edges per thread.
// ---------------------------------------------------------------------------
__global__ void __launch_bounds__(256) chain_kernel(const void* __restrict__ ei_raw,
                                                    int n_edges)
{
    __shared__ int s_is64;
    if (threadIdx.x == 0) s_is64 = sniff_is64(ei_raw);
    __syncthreads();
    int is64 = s_is64;

    int p = blockIdx.x * 256 + threadIdx.x;   // quad index
    int nq = n_edges >> 2;
    if (p < nq) {
        int e = p * 4;
        int s0, s1, s2, s3, t0, t1, t2, t3;
        if (is64) {
            const ulonglong2* ei2 = (const ulonglong2*)ei_raw;
            size_t tb = (size_t)(n_edges >> 1);
            ulonglong2 sa = ei2[2 * p],      sb  = ei2[2 * p + 1];
            ulonglong2 ta = ei2[tb + 2 * p], tbv = ei2[tb + 2 * p + 1];
            s0 = (int)sa.x; s1 = (int)sa.y; s2 = (int)sb.x; s3 = (int)sb.y;
            t0 = (int)ta.x; t1 = (int)ta.y; t2 = (int)tbv.x; t3 = (int)tbv.y;
        } else {
            const int4* ei4 = (const int4*)ei_raw;
            size_t tb = (size_t)(n_edges >> 2);
            int4 sv = ei4[p];
            int4 tv = ei4[tb + p];
            s0 = sv.x; s1 = sv.y; s2 = sv.z; s3 = sv.w;
            t0 = tv.x; t1 = tv.y; t2 = tv.z; t3 = tv.w;
        }
        int o0 = atomicExch(&g_head[s0], e + 1);
        int o1 = atomicExch(&g_head[s1], e + 2);
        int o2 = atomicExch(&g_head[s2], e + 3);
        int o3 = atomicExch(&g_head[s3], e + 4);
        g_link[e]     = make_int2(o0, t0);
        g_link[e + 1] = make_int2(o1, t1);
        g_link[e + 2] = make_int2(o2, t2);
        g_link[e + 3] = make_int2(o3, t3);
    } else if (p == nq) {
        for (int e = p * 4; e < n_edges; e++) {
            int src, tgt;
            if (is64) {
                const long long* ei = (const long long*)ei_raw;
                src = (int)ei[e];
                tgt = (int)ei[(size_t)n_edges + e];
            } else {
                const int* ei = (const int*)ei_raw;
                src = ei[e];
                tgt = ei[(size_t)n_edges + e];
            }
            int o = atomicExch(&g_head[src], e + 1);
            g_link[e] = make_int2(o, tgt);
        }
    }
}

// ---------------------------------------------------------------------------
// Kernel 3: chain-walk gather-reduce + mean. 8 lanes per node; lane j owns
// 16B (8 fp16) of the 128B row. All lanes chase the same list (broadcast 8B
// link loads); row gathers are coalesced 128B lines. Accumulate fp32, write
// once. Resets g_head[n]=0 for the next graph replay.
// ---------------------------------------------------------------------------
__global__ void __launch_bounds__(256) accumulate_kernel(float4* __restrict__ out4,
                                                         int n_nodes)
{
    int t = blockIdx.x * 256 + threadIdx.x;
    int n = t >> 3;
    int j = t & 7;
    if (n >= n_nodes) return;

    int e1 = g_head[n];

    const uint4* hp = (const uint4*)g_h;   // row = 8 uint4
    float acc[8] = {0.f, 0.f, 0.f, 0.f, 0.f, 0.f, 0.f, 0.f};
    int deg = 0;

    while (e1) {
        int2 ln = __ldg(&g_link[e1 - 1]);
        uint4 v = hp[(size_t)ln.y * 8 + j];
        e1 = ln.x;
        deg++;
        #pragma unroll
        for (int q = 0; q < 4; q++) {
            unsigned int u = (&v.x)[q];
            float2 f = __half22float2(*(__half2*)&u);
            acc[2 * q]     += f.x;
            acc[2 * q + 1] += f.y;
        }
    }

    if (j == 0) g_head[n] = 0;   // restore invariant for next replay

    float inv = 1.0f / fmaxf((float)deg, 1.0f);
    size_t base = (size_t)n * 16 + 2 * j;   // lane j owns floats [8j, 8j+8)
    out4[base]     = make_float4(acc[0] * inv, acc[1] * inv, acc[2] * inv, acc[3] * inv);
    out4[base + 1] = make_float4(acc[4] * inv, acc[5] * inv, acc[6] * inv, acc[7] * inv);
}

// ---------------------------------------------------------------------------
// Launch: gemm forked to a side stream; chain build on main stream; join
// before the chain-walk accumulate.
// ---------------------------------------------------------------------------
extern "C" void kernel_launch(void* const* d_in, const int* in_sizes, int n_in,
                              void* d_out, int out_size)
{
    const float* x  = (const float*)d_in[0];
    const void*  ei = d_in[1];
    const float* W  = (const float*)d_in[2];
    const float* b  = (const float*)d_in[3];
    float*       out = (float*)d_out;

    int N  = in_sizes[0] / EMBED;          // 100000
    int E  = in_sizes[1] / 2;              // 1600000
    int EQ = E / 4 + 1;                    // edge quads (+1 tail thread)
    int GB = (N + 255) / 256;              // gemm blocks (8 warps x 32 nodes)

    cudaStream_t s2;
    cudaEvent_t evFork, evJoin;
    cudaStreamCreateWithFlags(&s2, cudaStreamNonBlocking);
    cudaEventCreateWithFlags(&evFork, cudaEventDisableTiming);
    cudaEventCreateWithFlags(&evJoin, cudaEventDisableTiming);

    // Fork: gemm on side stream.
    cudaEventRecord(evFork, 0);
    cudaStreamWaitEvent(s2, evFork, 0);
    gemm_relu_kernel<<<GB, 256, 0, s2>>>(x, W, b, N);
    cudaEventRecord(evJoin, s2);

    // Main stream: build per-src linked lists.
    chain_kernel<<<(EQ + 255) / 256, 256>>>(ei, E);

    // Join, then walk the chains.
    cudaStreamWaitEvent(0, evJoin, 0);
    long long at = (long long)N * 8;
    accumulate_kernel<<<(int)((at + 255) / 256), 256>>>((float4*)out, N);
}

// round 12
// speedup vs baseline: 1.2372x; 1.0526x over previous
#include <cuda_runtime.h>
#include <cuda_fp16.h>

#define EMBED 64
#define MAX_NODES 100000
#define MAX_EDGES 1600000
#define WSTRIDE 68   // smem row stride (words) -> conflict-free B-fragment loads

// Scratch (zero-initialized at module load; accumulate re-zeroes g_head each
// run so graph replays always start from a clean state).
__device__ __half g_h[(size_t)MAX_NODES * EMBED];   // relu(x@W^T+b), fp16
__device__ int    g_head[2 * MAX_NODES];            // 2 parity chains per node; 0=empty
__device__ int2   g_link[MAX_EDGES];                // {next (0=end, else edge+1), tgt}

__device__ __forceinline__ unsigned int f2tf32(float v) {
    unsigned int r;
    asm("cvt.rna.tf32.f32 %0, %1;" : "=r"(r) : "f"(v));
    return r;
}

// Per-block inline dtype sniff: int64 edge data with node ids < 1e5 has zero
// high halves; int32 data packs two random ids per u64 word.
__device__ __forceinline__ int sniff_is64(const void* ei_raw) {
    const unsigned long long* e8 = (const unsigned long long*)ei_raw;
    int ok64 = 1;
    #pragma unroll
    for (int k = 0; k < 8; k++) {
        unsigned long long v = e8[k];
        if ((v >> 32) != 0ull || (v & 0xffffffffull) >= (1u << 28)) ok64 = 0;
    }
    return ok64;
}

// ---------------------------------------------------------------------------
// Kernel 1: h = relu(x @ W^T + b) via mma.sync.m16n8k8.tf32.
// One warp computes a 16-node x 64-output tile (8 k-tiles x 8 n-tiles).
// W staged in smem with stride 68 words: B-fragment access (4g + tig + k0)
// is a perfect bank permutation -> conflict-free LDS. Low register count
// keeps occupancy high. Epilogue fuses bias + ReLU + fp16 pack.
// ---------------------------------------------------------------------------
__global__ void __launch_bounds__(256) gemm_relu_kernel(
    const float* __restrict__ x,
    const float* __restrict__ W,
    const float* __restrict__ b,
    int n_nodes)
{
    __shared__ unsigned int ws[EMBED * WSTRIDE];  // W[o][k] tf32, padded rows
    __shared__ float bs[EMBED];

    int tid = threadIdx.x;
    for (int i = tid; i < EMBED * EMBED; i += 256) {
        int o = i >> 6, k = i & 63;
        ws[o * WSTRIDE + k] = f2tf32(W[i]);
    }
    if (tid < EMBED) bs[tid] = b[tid];
    __syncthreads();

    int warp = (blockIdx.x * 256 + tid) >> 5;
    int lane = tid & 31;
    int m0 = warp * 16;
    if (m0 >= n_nodes) return;

    int g   = lane >> 2;   // group 0..7
    int tig = lane & 3;    // 0..3

    int row0 = m0 + g;
    int row8 = m0 + g + 8;
    int r0c = (row0 < n_nodes) ? row0 : (n_nodes - 1);  // clamp for tails
    int r8c = (row8 < n_nodes) ? row8 : (n_nodes - 1);
    const float* xr0 = x + (size_t)r0c * EMBED;
    const float* xr8 = x + (size_t)r8c * EMBED;

    float c[8][4];
    #pragma unroll
    for (int nt = 0; nt < 8; nt++)
        c[nt][0] = c[nt][1] = c[nt][2] = c[nt][3] = 0.f;

    #pragma unroll
    for (int kt = 0; kt < 8; kt++) {
        int k0 = kt * 8;
        // A fragment (m16k8): a0=(g,tig) a1=(g+8,tig) a2=(g,tig+4) a3=(g+8,tig+4)
        unsigned int a0 = f2tf32(__ldg(xr0 + k0 + tig));
        unsigned int a1 = f2tf32(__ldg(xr8 + k0 + tig));
        unsigned int a2 = f2tf32(__ldg(xr0 + k0 + tig + 4));
        unsigned int a3 = f2tf32(__ldg(xr8 + k0 + tig + 4));
        #pragma unroll
        for (int nt = 0; nt < 8; nt++) {
            // B fragment (k8n8 col-major): B[k][n] = W[n][k], n = nt*8+g
            const unsigned int* wrow = ws + (nt * 8 + g) * WSTRIDE + k0 + tig;
            unsigned int b0 = wrow[0];
            unsigned int b1 = wrow[4];
            asm volatile(
                "mma.sync.aligned.m16n8k8.row.col.f32.tf32.tf32.f32 "
                "{%0,%1,%2,%3}, {%4,%5,%6,%7}, {%8,%9}, {%0,%1,%2,%3};"
                : "+f"(c[nt][0]), "+f"(c[nt][1]), "+f"(c[nt][2]), "+f"(c[nt][3])
                : "r"(a0), "r"(a1), "r"(a2), "r"(a3), "r"(b0), "r"(b1));
        }
    }

    // Epilogue: bias + relu + fp16 pack. c[nt] = {(g,2t),(g,2t+1),(g+8,2t),(g+8,2t+1)}
    unsigned int* hp = (unsigned int*)g_h;  // 2 halves per u32
    #pragma unroll
    for (int nt = 0; nt < 8; nt++) {
        int col = nt * 8 + 2 * tig;
        float b0v = bs[col], b1v = bs[col + 1];
        __half2 h0 = __floats2half2_rn(fmaxf(c[nt][0] + b0v, 0.f),
                                       fmaxf(c[nt][1] + b1v, 0.f));
        __half2 h1 = __floats2half2_rn(fmaxf(c[nt][2] + b0v, 0.f),
                                       fmaxf(c[nt][3] + b1v, 0.f));
        if (row0 < n_nodes)
            hp[((size_t)row0 * EMBED + col) >> 1] = *(unsigned int*)&h0;
        if (row8 < n_nodes)
            hp[((size_t)row8 * EMBED + col) >> 1] = *(unsigned int*)&h1;
    }
}

// ---------------------------------------------------------------------------
// Kernel 2: chain build. Edge e pushes onto parity chain head[2*src + (e&1)]
// and records {next, tgt} at g_link[e] (coalesced store). 4 edges per thread.
// ---------------------------------------------------------------------------
__global__ void __launch_bounds__(256) chain_kernel(const void* __restrict__ ei_raw,
                                                    int n_edges)
{
    __shared__ int s_is64;
    if (threadIdx.x == 0) s_is64 = sniff_is64(ei_raw);
    __syncthreads();
    int is64 = s_is64;

    int p = blockIdx.x * 256 + threadIdx.x;   // quad index
    int nq = n_edges >> 2;
    if (p < nq) {
        int e = p * 4;
        int s0, s1, s2, s3, t0, t1, t2, t3;
        if (is64) {
            const ulonglong2* ei2 = (const ulonglong2*)ei_raw;
            size_t tb = (size_t)(n_edges >> 1);
            ulonglong2 sa = ei2[2 * p],      sb  = ei2[2 * p + 1];
            ulonglong2 ta = ei2[tb + 2 * p], tbv = ei2[tb + 2 * p + 1];
            s0 = (int)sa.x; s1 = (int)sa.y; s2 = (int)sb.x; s3 = (int)sb.y;
            t0 = (int)ta.x; t1 = (int)ta.y; t2 = (int)tbv.x; t3 = (int)tbv.y;
        } else {
            const int4* ei4 = (const int4*)ei_raw;
            size_t tb = (size_t)(n_edges >> 2);
            int4 sv = ei4[p];
            int4 tv = ei4[tb + p];
            s0 = sv.x; s1 = sv.y; s2 = sv.z; s3 = sv.w;
            t0 = tv.x; t1 = tv.y; t2 = tv.z; t3 = tv.w;
        }
        // e is even: parities are 0,1,0,1 for e..e+3.
        int o0 = atomicExch(&g_head[2 * s0],     e + 1);
        int o1 = atomicExch(&g_head[2 * s1 + 1], e + 2);
        int o2 = atomicExch(&g_head[2 * s2],     e + 3);
        int o3 = atomicExch(&g_head[2 * s3 + 1], e + 4);
        g_link[e]     = make_int2(o0, t0);
        g_link[e + 1] = make_int2(o1, t1);
        g_link[e + 2] = make_int2(o2, t2);
        g_link[e + 3] = make_int2(o3, t3);
    } else if (p == nq) {
        for (int e = p * 4; e < n_edges; e++) {
            int src, tgt;
            if (is64) {
                const long long* ei = (const long long*)ei_raw;
                src = (int)ei[e];
                tgt = (int)ei[(size_t)n_edges + e];
            } else {
                const int* ei = (const int*)ei_raw;
                src = ei[e];
                tgt = ei[(size_t)n_edges + e];
            }
            int o = atomicExch(&g_head[2 * src + (e & 1)], e + 1);
            g_link[e] = make_int2(o, tgt);
        }
    }
}

// ---------------------------------------------------------------------------
// Kernel 3: chain-walk gather-reduce + mean. 16 lanes per node: two 8-lane
// sub-groups each walk one parity chain (halving serial chase depth); lane j
// owns 16B (8 fp16) of the 128B row. Sub-group results combined via
// shfl_xor(8). Resets both heads for the next graph replay.
// ---------------------------------------------------------------------------
__global__ void __launch_bounds__(256) accumulate_kernel(float4* __restrict__ out4,
                                                         int n_nodes)
{
    int t = blockIdx.x * 256 + threadIdx.x;
    int n   = t >> 4;
    int sub = (t >> 3) & 1;
    int j   = t & 7;
    if (n >= n_nodes) return;

    int e1 = g_head[2 * n + sub];

    const uint4* hp = (const uint4*)g_h;   // row = 8 uint4
    float acc[8] = {0.f, 0.f, 0.f, 0.f, 0.f, 0.f, 0.f, 0.f};
    int deg = 0;

    while (e1) {
        int2 ln = __ldg(&g_link[e1 - 1]);
        uint4 v = hp[(size_t)ln.y * 8 + j];
        e1 = ln.x;
        deg++;
        #pragma unroll
        for (int q = 0; q < 4; q++) {
            unsigned int u = (&v.x)[q];
            float2 f = __half22float2(*(__half2*)&u);
            acc[2 * q]     += f.x;
            acc[2 * q + 1] += f.y;
        }
    }

    if (j == 0) g_head[2 * n + sub] = 0;   // restore invariant for next replay

    // Combine the two parity chains (lanes differing in bit 3).
    deg += __shfl_xor_sync(0xffffffffu, deg, 8);
    #pragma unroll
    for (int q = 0; q < 8; q++)
        acc[q] += __shfl_xor_sync(0xffffffffu, acc[q], 8);

    if (sub == 0) {
        float inv = 1.0f / fmaxf((float)deg, 1.0f);
        size_t base = (size_t)n * 16 + 2 * j;   // lane j owns floats [8j, 8j+8)
        out4[base]     = make_float4(acc[0] * inv, acc[1] * inv, acc[2] * inv, acc[3] * inv);
        out4[base + 1] = make_float4(acc[4] * inv, acc[5] * inv, acc[6] * inv, acc[7] * inv);
    }
}

// ---------------------------------------------------------------------------
// Launch: gemm forked to a side stream; chain build on main stream; join
// before the chain-walk accumulate.
// ---------------------------------------------------------------------------
extern "C" void kernel_launch(void* const* d_in, const int* in_sizes, int n_in,
                              void* d_out, int out_size)
{
    const float* x  = (const float*)d_in[0];
    const void*  ei = d_in[1];
    const float* W  = (const float*)d_in[2];
    const float* b  = (const float*)d_in[3];
    float*       out = (float*)d_out;

    int N  = in_sizes[0] / EMBED;          // 100000
    int E  = in_sizes[1] / 2;              // 1600000
    int EQ = E / 4 + 1;                    // edge quads (+1 tail thread)
    int GB = (N + 127) / 128;              // gemm blocks (8 warps x 16 nodes)

    cudaStream_t s2;
    cudaEvent_t evFork, evJoin;
    cudaStreamCreateWithFlags(&s2, cudaStreamNonBlocking);
    cudaEventCreateWithFlags(&evFork, cudaEventDisableTiming);
    cudaEventCreateWithFlags(&evJoin, cudaEventDisableTiming);

    // Fork: gemm on side stream.
    cudaEventRecord(evFork, 0);
    cudaStreamWaitEvent(s2, evFork, 0);
    gemm_relu_kernel<<<GB, 256, 0, s2>>>(x, W, b, N);
    cudaEventRecord(evJoin, s2);

    // Main stream: build per-src parity chains.
    chain_kernel<<<(EQ + 255) / 256, 256>>>(ei, E);

    // Join, then walk the chains.
    cudaStreamWaitEvent(0, evJoin, 0);
    long long at = (long long)N * 16;
    accumulate_kernel<<<(int)((at + 255) / 256), 256>>>((float4*)out, N);
}

// round 13
// speedup vs baseline: 1.3288x; 1.0741x over previous
#include <cuda_runtime.h>
#include <cuda_fp16.h>

#define EMBED 64
#define MAX_NODES 100000
#define MAX_EDGES 1600000
#define WPSTRIDE 36   // smem stride (u32) for packed W -> bank = 4g+tig, conflict-free

// Scratch (zero-initialized at module load; accumulate re-zeroes g_head each
// run so graph replays always start from a clean state).
__device__ __half g_h[(size_t)MAX_NODES * EMBED];   // relu(x@W^T+b), fp16
__device__ int    g_head[2 * MAX_NODES];            // 2 parity chains per node; 0=empty
__device__ int2   g_link[MAX_EDGES];                // {next (0=end, else edge+1), tgt}

// Per-block inline dtype sniff: int64 edge data with node ids < 1e5 has zero
// high halves; int32 data packs two random ids per u64 word.
__device__ __forceinline__ int sniff_is64(const void* ei_raw) {
    const unsigned long long* e8 = (const unsigned long long*)ei_raw;
    int ok64 = 1;
    #pragma unroll
    for (int k = 0; k < 8; k++) {
        unsigned long long v = e8[k];
        if ((v >> 32) != 0ull || (v & 0xffffffffull) >= (1u << 28)) ok64 = 0;
    }
    return ok64;
}

__device__ __forceinline__ unsigned int pack_h2(float lo, float hi) {
    __half2 h = __floats2half2_rn(lo, hi);
    return *(unsigned int*)&h;
}

// ---------------------------------------------------------------------------
// Kernel 1: h = relu(x @ W^T + b) via mma.sync.m16n8k16.f16 (f32 accum).
// One warp computes a 16-node x 64-output tile: 4 k-chunks x 8 n-tiles = 32
// MMA. W pre-packed to half2 in smem (stride 36 u32, conflict-free); A
// fragments are float2 loads from x packed to half2. fp16 and tf32 share an
// 11-bit mantissa -> same precision as the previous tf32 version.
// ---------------------------------------------------------------------------
__global__ void __launch_bounds__(256) gemm_relu_kernel(
    const float* __restrict__ x,
    const float* __restrict__ W,
    const float* __restrict__ b,
    int n_nodes)
{
    __shared__ unsigned int wp[EMBED * WPSTRIDE];  // wp[o][kk] = half2(W[o][2kk], W[o][2kk+1])
    __shared__ float bs[EMBED];

    int tid = threadIdx.x;
    for (int i = tid; i < EMBED * 32; i += 256) {
        int o = i >> 5, kk = i & 31;
        const float2 v = *(const float2*)(W + o * EMBED + 2 * kk);
        wp[o * WPSTRIDE + kk] = pack_h2(v.x, v.y);
    }
    if (tid < EMBED) bs[tid] = b[tid];
    __syncthreads();

    int warp = (blockIdx.x * 256 + tid) >> 5;
    int lane = tid & 31;
    int m0 = warp * 16;
    if (m0 >= n_nodes) return;

    int g   = lane >> 2;   // group 0..7
    int tig = lane & 3;    // 0..3

    int row0 = m0 + g;
    int row8 = m0 + g + 8;
    int r0c = (row0 < n_nodes) ? row0 : (n_nodes - 1);  // clamp for tails
    int r8c = (row8 < n_nodes) ? row8 : (n_nodes - 1);
    const float* xr0 = x + (size_t)r0c * EMBED;
    const float* xr8 = x + (size_t)r8c * EMBED;

    float c[8][4];
    #pragma unroll
    for (int nt = 0; nt < 8; nt++)
        c[nt][0] = c[nt][1] = c[nt][2] = c[nt][3] = 0.f;

    #pragma unroll
    for (int kt = 0; kt < 4; kt++) {
        int k0 = kt * 16;
        // A fragment (m16k16 f16): a0=(g, 2tig..+1) a1=(g+8, 2tig..+1)
        //                          a2=(g, 2tig+8..+9) a3=(g+8, 2tig+8..+9)
        float2 p00 = *(const float2*)(xr0 + k0 + 2 * tig);
        float2 p08 = *(const float2*)(xr0 + k0 + 2 * tig + 8);
        float2 p80 = *(const float2*)(xr8 + k0 + 2 * tig);
        float2 p88 = *(const float2*)(xr8 + k0 + 2 * tig + 8);
        unsigned int a0 = pack_h2(p00.x, p00.y);
        unsigned int a1 = pack_h2(p80.x, p80.y);
        unsigned int a2 = pack_h2(p08.x, p08.y);
        unsigned int a3 = pack_h2(p88.x, p88.y);
        #pragma unroll
        for (int nt = 0; nt < 8; nt++) {
            // B fragment (k16n8 col-major): B[k][n] = W[n][k], n = nt*8+g
            // b0 = {W[n][k0+2tig], +1}, b1 = {W[n][k0+2tig+8], +9}
            const unsigned int* wrow = wp + (nt * 8 + g) * WPSTRIDE + 8 * kt + tig;
            unsigned int b0 = wrow[0];
            unsigned int b1 = wrow[4];
            asm volatile(
                "mma.sync.aligned.m16n8k16.row.col.f32.f16.f16.f32 "
                "{%0,%1,%2,%3}, {%4,%5,%6,%7}, {%8,%9}, {%0,%1,%2,%3};"
                : "+f"(c[nt][0]), "+f"(c[nt][1]), "+f"(c[nt][2]), "+f"(c[nt][3])
                : "r"(a0), "r"(a1), "r"(a2), "r"(a3), "r"(b0), "r"(b1));
        }
    }

    // Epilogue: bias + relu + fp16 pack. c[nt] = {(g,2t),(g,2t+1),(g+8,2t),(g+8,2t+1)}
    unsigned int* hp = (unsigned int*)g_h;  // 2 halves per u32
    #pragma unroll
    for (int nt = 0; nt < 8; nt++) {
        int col = nt * 8 + 2 * tig;
        float b0v = bs[col], b1v = bs[col + 1];
        unsigned int h0 = pack_h2(fmaxf(c[nt][0] + b0v, 0.f),
                                  fmaxf(c[nt][1] + b1v, 0.f));
        unsigned int h1 = pack_h2(fmaxf(c[nt][2] + b0v, 0.f),
                                  fmaxf(c[nt][3] + b1v, 0.f));
        if (row0 < n_nodes)
            hp[((size_t)row0 * EMBED + col) >> 1] = h0;
        if (row8 < n_nodes)
            hp[((size_t)row8 * EMBED + col) >> 1] = h1;
    }
}

// ---------------------------------------------------------------------------
// Kernel 2: chain build. Edge e pushes onto parity chain head[2*src + (e&1)]
// and records {next, tgt} at g_link[e] (coalesced store). 4 edges per thread.
// ---------------------------------------------------------------------------
__global__ void __launch_bounds__(256) chain_kernel(const void* __restrict__ ei_raw,
                                                    int n_edges)
{
    __shared__ int s_is64;
    if (threadIdx.x == 0) s_is64 = sniff_is64(ei_raw);
    __syncthreads();
    int is64 = s_is64;

    int p = blockIdx.x * 256 + threadIdx.x;   // quad index
    int nq = n_edges >> 2;
    if (p < nq) {
        int e = p * 4;
        int s0, s1, s2, s3, t0, t1, t2, t3;
        if (is64) {
            const ulonglong2* ei2 = (const ulonglong2*)ei_raw;
            size_t tb = (size_t)(n_edges >> 1);
            ulonglong2 sa = ei2[2 * p],      sb  = ei2[2 * p + 1];
            ulonglong2 ta = ei2[tb + 2 * p], tbv = ei2[tb + 2 * p + 1];
            s0 = (int)sa.x; s1 = (int)sa.y; s2 = (int)sb.x; s3 = (int)sb.y;
            t0 = (int)ta.x; t1 = (int)ta.y; t2 = (int)tbv.x; t3 = (int)tbv.y;
        } else {
            const int4* ei4 = (const int4*)ei_raw;
            size_t tb = (size_t)(n_edges >> 2);
            int4 sv = ei4[p];
            int4 tv = ei4[tb + p];
            s0 = sv.x; s1 = sv.y; s2 = sv.z; s3 = sv.w;
            t0 = tv.x; t1 = tv.y; t2 = tv.z; t3 = tv.w;
        }
        // e is even: parities are 0,1,0,1 for e..e+3.
        int o0 = atomicExch(&g_head[2 * s0],     e + 1);
        int o1 = atomicExch(&g_head[2 * s1 + 1], e + 2);
        int o2 = atomicExch(&g_head[2 * s2],     e + 3);
        int o3 = atomicExch(&g_head[2 * s3 + 1], e + 4);
        g_link[e]     = make_int2(o0, t0);
        g_link[e + 1] = make_int2(o1, t1);
        g_link[e + 2] = make_int2(o2, t2);
        g_link[e + 3] = make_int2(o3, t3);
    } else if (p == nq) {
        for (int e = p * 4; e < n_edges; e++) {
            int src, tgt;
            if (is64) {
                const long long* ei = (const long long*)ei_raw;
                src = (int)ei[e];
                tgt = (int)ei[(size_t)n_edges + e];
            } else {
                const int* ei = (const int*)ei_raw;
                src = ei[e];
                tgt = ei[(size_t)n_edges + e];
            }
            int o = atomicExch(&g_head[2 * src + (e & 1)], e + 1);
            g_link[e] = make_int2(o, tgt);
        }
    }
}

// ---------------------------------------------------------------------------
// Kernel 3: chain-walk gather-reduce + mean. 8 lanes per node; lane j owns
// 16B (8 fp16) of the 128B row. Each group walks BOTH parity chains with two
// independent cursors -> 2 link + 2 row loads in flight per iteration,
// half the serial chase depth, and 2.7 thread-waves instead of 5.3.
// Resets both heads for the next graph replay.
// ---------------------------------------------------------------------------
__global__ void __launch_bounds__(256) accumulate_kernel(float4* __restrict__ out4,
                                                         int n_nodes)
{
    int t = blockIdx.x * 256 + threadIdx.x;
    int n = t >> 3;
    int j = t & 7;
    if (n >= n_nodes) return;

    int e1 = g_head[2 * n];
    int e2 = g_head[2 * n + 1];

    const uint4* hp = (const uint4*)g_h;   // row = 8 uint4
    float acc[8] = {0.f, 0.f, 0.f, 0.f, 0.f, 0.f, 0.f, 0.f};
    int deg = 0;

    while (e1 | e2) {
        int2 l1, l2;
        bool h1 = (e1 != 0), h2 = (e2 != 0);
        if (h1) l1 = __ldg(&g_link[e1 - 1]);
        if (h2) l2 = __ldg(&g_link[e2 - 1]);
        if (h1) {
            uint4 v = hp[(size_t)l1.y * 8 + j];
            e1 = l1.x;
            deg++;
            #pragma unroll
            for (int q = 0; q < 4; q++) {
                unsigned int u = (&v.x)[q];
                float2 f = __half22float2(*(__half2*)&u);
                acc[2 * q]     += f.x;
                acc[2 * q + 1] += f.y;
            }
        }
        if (h2) {
            uint4 v = hp[(size_t)l2.y * 8 + j];
            e2 = l2.x;
            deg++;
            #pragma unroll
            for (int q = 0; q < 4; q++) {
                unsigned int u = (&v.x)[q];
                float2 f = __half22float2(*(__half2*)&u);
                acc[2 * q]     += f.x;
                acc[2 * q + 1] += f.y;
            }
        }
    }

    if (j == 0) {   // restore invariant for next replay
        g_head[2 * n]     = 0;
        g_head[2 * n + 1] = 0;
    }

    float inv = 1.0f / fmaxf((float)deg, 1.0f);
    size_t base = (size_t)n * 16 + 2 * j;   // lane j owns floats [8j, 8j+8)
    out4[base]     = make_float4(acc[0] * inv, acc[1] * inv, acc[2] * inv, acc[3] * inv);
    out4[base + 1] = make_float4(acc[4] * inv, acc[5] * inv, acc[6] * inv, acc[7] * inv);
}

// ---------------------------------------------------------------------------
// Launch: gemm forked to a side stream; chain build on main stream; join
// before the chain-walk accumulate.
// ---------------------------------------------------------------------------
extern "C" void kernel_launch(void* const* d_in, const int* in_sizes, int n_in,
                              void* d_out, int out_size)
{
    const float* x  = (const float*)d_in[0];
    const void*  ei = d_in[1];
    const float* W  = (const float*)d_in[2];
    const float* b  = (const float*)d_in[3];
    float*       out = (float*)d_out;

    int N  = in_sizes[0] / EMBED;          // 100000
    int E  = in_sizes[1] / 2;              // 1600000
    int EQ = E / 4 + 1;                    // edge quads (+1 tail thread)
    int GB = (N + 127) / 128;              // gemm blocks (8 warps x 16 nodes)

    cudaStream_t s2;
    cudaEvent_t evFork, evJoin;
    cudaStreamCreateWithFlags(&s2, cudaStreamNonBlocking);
    cudaEventCreateWithFlags(&evFork, cudaEventDisableTiming);
    cudaEventCreateWithFlags(&evJoin, cudaEventDisableTiming);

    // Fork: gemm on side stream.
    cudaEventRecord(evFork, 0);
    cudaStreamWaitEvent(s2, evFork, 0);
    gemm_relu_kernel<<<GB, 256, 0, s2>>>(x, W, b, N);
    cudaEventRecord(evJoin, s2);

    // Main stream: build per-src parity chains.
    chain_kernel<<<(EQ + 255) / 256, 256>>>(ei, E);

    // Join, then walk the chains.
    cudaStreamWaitEvent(0, evJoin, 0);
    long long at = (long long)N * 8;
    accumulate_kernel<<<(int)((at + 255) / 256), 256>>>((float4*)out, N);
}

// round 14
// speedup vs baseline: 1.3458x; 1.0128x over previous
#include <cuda_runtime.h>
#include <cuda_fp16.h>

#define EMBED 64
#define MAX_NODES 100000
#define MAX_EDGES 1600000
#define WPSTRIDE 36   // smem stride (u32) for packed W -> bank = 4g+tig, conflict-free

// Scratch (zero-initialized at module load; accumulate re-zeroes g_head each
// run so graph replays always start from a clean state).
__device__ __half g_h[(size_t)MAX_NODES * EMBED];   // relu(x@W^T+b), fp16
__device__ int    g_head[4 * MAX_NODES];            // 4 parity chains per node; 0=empty
__device__ int2   g_link[MAX_EDGES];                // {next (0=end, else edge+1), tgt}

// Per-block inline dtype sniff: int64 edge data with node ids < 1e5 has zero
// high halves; int32 data packs two random ids per u64 word.
__device__ __forceinline__ int sniff_is64(const void* ei_raw) {
    const unsigned long long* e8 = (const unsigned long long*)ei_raw;
    int ok64 = 1;
    #pragma unroll
    for (int k = 0; k < 8; k++) {
        unsigned long long v = e8[k];
        if ((v >> 32) != 0ull || (v & 0xffffffffull) >= (1u << 28)) ok64 = 0;
    }
    return ok64;
}

__device__ __forceinline__ unsigned int pack_h2(float lo, float hi) {
    __half2 h = __floats2half2_rn(lo, hi);
    return *(unsigned int*)&h;
}

// ---------------------------------------------------------------------------
// Kernel 1: h = relu(x @ W^T + b) via mma.sync.m16n8k16.f16 (f32 accum).
// One warp computes a 16-node x 64-output tile: 4 k-chunks x 8 n-tiles = 32
// MMA. ALL 16 A-fragment loads are hoisted ahead of the MMA loop (MLP=16);
// W pre-packed to half2 in smem (stride 36 u32, conflict-free bank perm).
// ---------------------------------------------------------------------------
__global__ void __launch_bounds__(256) gemm_relu_kernel(
    const float* __restrict__ x,
    const float* __restrict__ W,
    const float* __restrict__ b,
    int n_nodes)
{
    __shared__ unsigned int wp[EMBED * WPSTRIDE];  // wp[o][kk] = half2(W[o][2kk], W[o][2kk+1])
    __shared__ float bs[EMBED];

    int tid = threadIdx.x;
    for (int i = tid; i < EMBED * 32; i += 256) {
        int o = i >> 5, kk = i & 31;
        const float2 v = *(const float2*)(W + o * EMBED + 2 * kk);
        wp[o * WPSTRIDE + kk] = pack_h2(v.x, v.y);
    }
    if (tid < EMBED) bs[tid] = b[tid];
    __syncthreads();

    int warp = (blockIdx.x * 256 + tid) >> 5;
    int lane = tid & 31;
    int m0 = warp * 16;
    if (m0 >= n_nodes) return;

    int g   = lane >> 2;   // group 0..7
    int tig = lane & 3;    // 0..3

    int row0 = m0 + g;
    int row8 = m0 + g + 8;
    int r0c = (row0 < n_nodes) ? row0 : (n_nodes - 1);  // clamp for tails
    int r8c = (row8 < n_nodes) ? row8 : (n_nodes - 1);
    const float* xr0 = x + (size_t)r0c * EMBED;
    const float* xr8 = x + (size_t)r8c * EMBED;

    // Hoist all A fragments: a[kt][0..3], packed half2.
    unsigned int a[4][4];
    #pragma unroll
    for (int kt = 0; kt < 4; kt++) {
        int k0 = kt * 16;
        float2 p00 = *(const float2*)(xr0 + k0 + 2 * tig);
        float2 p80 = *(const float2*)(xr8 + k0 + 2 * tig);
        float2 p08 = *(const float2*)(xr0 + k0 + 2 * tig + 8);
        float2 p88 = *(const float2*)(xr8 + k0 + 2 * tig + 8);
        a[kt][0] = pack_h2(p00.x, p00.y);
        a[kt][1] = pack_h2(p80.x, p80.y);
        a[kt][2] = pack_h2(p08.x, p08.y);
        a[kt][3] = pack_h2(p88.x, p88.y);
    }

    float c[8][4];
    #pragma unroll
    for (int nt = 0; nt < 8; nt++)
        c[nt][0] = c[nt][1] = c[nt][2] = c[nt][3] = 0.f;

    #pragma unroll
    for (int kt = 0; kt < 4; kt++) {
        #pragma unroll
        for (int nt = 0; nt < 8; nt++) {
            // B fragment (k16n8 col-major): B[k][n] = W[n][k], n = nt*8+g
            const unsigned int* wrow = wp + (nt * 8 + g) * WPSTRIDE + 8 * kt + tig;
            unsigned int b0 = wrow[0];
            unsigned int b1 = wrow[4];
            asm volatile(
                "mma.sync.aligned.m16n8k16.row.col.f32.f16.f16.f32 "
                "{%0,%1,%2,%3}, {%4,%5,%6,%7}, {%8,%9}, {%0,%1,%2,%3};"
                : "+f"(c[nt][0]), "+f"(c[nt][1]), "+f"(c[nt][2]), "+f"(c[nt][3])
                : "r"(a[kt][0]), "r"(a[kt][1]), "r"(a[kt][2]), "r"(a[kt][3]),
                  "r"(b0), "r"(b1));
        }
    }

    // Epilogue: bias + relu + fp16 pack. c[nt] = {(g,2t),(g,2t+1),(g+8,2t),(g+8,2t+1)}
    unsigned int* hp = (unsigned int*)g_h;  // 2 halves per u32
    #pragma unroll
    for (int nt = 0; nt < 8; nt++) {
        int col = nt * 8 + 2 * tig;
        float b0v = bs[col], b1v = bs[col + 1];
        unsigned int h0 = pack_h2(fmaxf(c[nt][0] + b0v, 0.f),
                                  fmaxf(c[nt][1] + b1v, 0.f));
        unsigned int h1 = pack_h2(fmaxf(c[nt][2] + b0v, 0.f),
                                  fmaxf(c[nt][3] + b1v, 0.f));
        if (row0 < n_nodes)
            hp[((size_t)row0 * EMBED + col) >> 1] = h0;
        if (row8 < n_nodes)
            hp[((size_t)row8 * EMBED + col) >> 1] = h1;
    }
}

// ---------------------------------------------------------------------------
// Kernel 2: chain build. Edge e pushes onto parity chain head[4*src + (e&3)]
// and records {next, tgt} at g_link[e] (coalesced store). 4 edges per thread
// (quad-aligned: parities are exactly 0,1,2,3).
// ---------------------------------------------------------------------------
__global__ void __launch_bounds__(256) chain_kernel(const void* __restrict__ ei_raw,
                                                    int n_edges)
{
    __shared__ int s_is64;
    if (threadIdx.x == 0) s_is64 = sniff_is64(ei_raw);
    __syncthreads();
    int is64 = s_is64;

    int p = blockIdx.x * 256 + threadIdx.x;   // quad index
    int nq = n_edges >> 2;
    if (p < nq) {
        int e = p * 4;
        int s0, s1, s2, s3, t0, t1, t2, t3;
        if (is64) {
            const ulonglong2* ei2 = (const ulonglong2*)ei_raw;
            size_t tb = (size_t)(n_edges >> 1);
            ulonglong2 sa = ei2[2 * p],      sb  = ei2[2 * p + 1];
            ulonglong2 ta = ei2[tb + 2 * p], tbv = ei2[tb + 2 * p + 1];
            s0 = (int)sa.x; s1 = (int)sa.y; s2 = (int)sb.x; s3 = (int)sb.y;
            t0 = (int)ta.x; t1 = (int)ta.y; t2 = (int)tbv.x; t3 = (int)tbv.y;
        } else {
            const int4* ei4 = (const int4*)ei_raw;
            size_t tb = (size_t)(n_edges >> 2);
            int4 sv = ei4[p];
            int4 tv = ei4[tb + p];
            s0 = sv.x; s1 = sv.y; s2 = sv.z; s3 = sv.w;
            t0 = tv.x; t1 = tv.y; t2 = tv.z; t3 = tv.w;
        }
        int o0 = atomicExch(&g_head[4 * s0],     e + 1);
        int o1 = atomicExch(&g_head[4 * s1 + 1], e + 2);
        int o2 = atomicExch(&g_head[4 * s2 + 2], e + 3);
        int o3 = atomicExch(&g_head[4 * s3 + 3], e + 4);
        g_link[e]     = make_int2(o0, t0);
        g_link[e + 1] = make_int2(o1, t1);
        g_link[e + 2] = make_int2(o2, t2);
        g_link[e + 3] = make_int2(o3, t3);
    } else if (p == nq) {
        for (int e = p * 4; e < n_edges; e++) {
            int src, tgt;
            if (is64) {
                const long long* ei = (const long long*)ei_raw;
                src = (int)ei[e];
                tgt = (int)ei[(size_t)n_edges + e];
            } else {
                const int* ei = (const int*)ei_raw;
                src = ei[e];
                tgt = ei[(size_t)n_edges + e];
            }
            int o = atomicExch(&g_head[4 * src + (e & 3)], e + 1);
            g_link[e] = make_int2(o, tgt);
        }
    }
}

// ---------------------------------------------------------------------------
// Kernel 3: chain-walk gather-reduce + mean. 8 lanes per node; lane j owns
// 16B (8 fp16) of the 128B row. Each group walks FOUR parity chains with
// independent cursors -> 4 link + up to 4 row loads in flight per iteration,
// serial chase depth ~4. Resets all 4 heads for the next graph replay.
// ---------------------------------------------------------------------------
__global__ void __launch_bounds__(256) accumulate_kernel(float4* __restrict__ out4,
                                                         int n_nodes)
{
    int t = blockIdx.x * 256 + threadIdx.x;
    int n = t >> 3;
    int j = t & 7;
    if (n >= n_nodes) return;

    int cur[4];
    #pragma unroll
    for (int q = 0; q < 4; q++) cur[q] = g_head[4 * n + q];

    const uint4* hp = (const uint4*)g_h;   // row = 8 uint4
    float acc[8] = {0.f, 0.f, 0.f, 0.f, 0.f, 0.f, 0.f, 0.f};
    int deg = 0;

    while (cur[0] | cur[1] | cur[2] | cur[3]) {
        int2 ln[4];
        #pragma unroll
        for (int q = 0; q < 4; q++)
            if (cur[q]) ln[q] = __ldg(&g_link[cur[q] - 1]);
        #pragma unroll
        for (int q = 0; q < 4; q++) {
            if (cur[q]) {
                uint4 v = hp[(size_t)ln[q].y * 8 + j];
                cur[q] = ln[q].x;
                deg++;
                #pragma unroll
                for (int w = 0; w < 4; w++) {
                    unsigned int u = (&v.x)[w];
                    float2 f = __half22float2(*(__half2*)&u);
                    acc[2 * w]     += f.x;
                    acc[2 * w + 1] += f.y;
                }
            }
        }
    }

    if (j < 4) g_head[4 * n + j] = 0;   // restore invariant for next replay

    float inv = 1.0f / fmaxf((float)deg, 1.0f);
    size_t base = (size_t)n * 16 + 2 * j;   // lane j owns floats [8j, 8j+8)
    out4[base]     = make_float4(acc[0] * inv, acc[1] * inv, acc[2] * inv, acc[3] * inv);
    out4[base + 1] = make_float4(acc[4] * inv, acc[5] * inv, acc[6] * inv, acc[7] * inv);
}

// ---------------------------------------------------------------------------
// Launch: gemm forked to a side stream; chain build on main stream; join
// before the chain-walk accumulate.
// ---------------------------------------------------------------------------
extern "C" void kernel_launch(void* const* d_in, const int* in_sizes, int n_in,
                              void* d_out, int out_size)
{
    const float* x  = (const float*)d_in[0];
    const void*  ei = d_in[1];
    const float* W  = (const float*)d_in[2];
    const float* b  = (const float*)d_in[3];
    float*       out = (float*)d_out;

    int N  = in_sizes[0] / EMBED;          // 100000
    int E  = in_sizes[1] / 2;              // 1600000
    int EQ = E / 4 + 1;                    // edge quads (+1 tail thread)
    int GB = (N + 127) / 128;              // gemm blocks (8 warps x 16 nodes)

    cudaStream_t s2;
    cudaEvent_t evFork, evJoin;
    cudaStreamCreateWithFlags(&s2, cudaStreamNonBlocking);
    cudaEventCreateWithFlags(&evFork, cudaEventDisableTiming);
    cudaEventCreateWithFlags(&evJoin, cudaEventDisableTiming);

    // Fork: gemm on side stream.
    cudaEventRecord(evFork, 0);
    cudaStreamWaitEvent(s2, evFork, 0);
    gemm_relu_kernel<<<GB, 256, 0, s2>>>(x, W, b, N);
    cudaEventRecord(evJoin, s2);

    // Main stream: build per-src parity chains.
    chain_kernel<<<(EQ + 255) / 256, 256>>>(ei, E);

    // Join, then walk the chains.
    cudaStreamWaitEvent(0, evJoin, 0);
    long long at = (long long)N * 8;
    accumulate_kernel<<<(int)((at + 255) / 256), 256>>>((float4*)out, N);
}

// round 15
// speedup vs baseline: 1.3465x; 1.0005x over previous
#include <cuda_runtime.h>
#include <cuda_fp16.h>

#define EMBED 64
#define MAX_NODES 100000
#define MAX_EDGES 1600000
#define WPSTRIDE 36   // smem stride (u32) for packed W -> bank = 4g+tig, conflict-free

// Scratch (zero-initialized at module load; accumulate re-zeroes g_head each
// run so graph replays always start from a clean state).
__device__ __half g_h[(size_t)MAX_NODES * EMBED];   // relu(x@W^T+b), fp16
__device__ int    g_head[4 * MAX_NODES];            // 4 parity chains per node; 0=empty
__device__ int2   g_link[MAX_EDGES];                // {next (0=end, else edge+1), tgt}

// Per-block inline dtype sniff: int64 edge data with node ids < 1e5 has zero
// high halves; int32 data packs two random ids per u64 word.
__device__ __forceinline__ int sniff_is64(const void* ei_raw) {
    const unsigned long long* e8 = (const unsigned long long*)ei_raw;
    int ok64 = 1;
    #pragma unroll
    for (int k = 0; k < 8; k++) {
        unsigned long long v = e8[k];
        if ((v >> 32) != 0ull || (v & 0xffffffffull) >= (1u << 28)) ok64 = 0;
    }
    return ok64;
}

__device__ __forceinline__ unsigned int pack_h2(float lo, float hi) {
    __half2 h = __floats2half2_rn(lo, hi);
    return *(unsigned int*)&h;
}

// ---------------------------------------------------------------------------
// Kernel 1: h = relu(x @ W^T + b) via mma.sync.m16n8k16.f16 (f32 accum).
// GRID-STRIDE over 16-node tiles: 296 blocks (2/SM, one full wave), W staged
// once per block and reused across ~2.6 tiles per warp. Per tile: 16 hoisted
// A-fragment loads (MLP=16), 32 MMAs, conflict-free smem B reads.
// ---------------------------------------------------------------------------
__global__ void __launch_bounds__(256) gemm_relu_kernel(
    const float* __restrict__ x,
    const float* __restrict__ W,
    const float* __restrict__ b,
    int n_nodes)
{
    __shared__ unsigned int wp[EMBED * WPSTRIDE];  // wp[o][kk] = half2(W[o][2kk], W[o][2kk+1])
    __shared__ float bs[EMBED];

    int tid = threadIdx.x;
    for (int i = tid; i < EMBED * 32; i += 256) {
        int o = i >> 5, kk = i & 31;
        const float2 v = *(const float2*)(W + o * EMBED + 2 * kk);
        wp[o * WPSTRIDE + kk] = pack_h2(v.x, v.y);
    }
    if (tid < EMBED) bs[tid] = b[tid];
    __syncthreads();

    int lane = tid & 31;
    int g   = lane >> 2;   // group 0..7
    int tig = lane & 3;    // 0..3

    int warp0  = (blockIdx.x * 256 + tid) >> 5;
    int nwarps = (gridDim.x * 256) >> 5;
    int ntiles = (n_nodes + 15) >> 4;

    for (int tile = warp0; tile < ntiles; tile += nwarps) {
        int m0 = tile * 16;
        int row0 = m0 + g;
        int row8 = m0 + g + 8;
        int r0c = (row0 < n_nodes) ? row0 : (n_nodes - 1);  // clamp for tails
        int r8c = (row8 < n_nodes) ? row8 : (n_nodes - 1);
        const float* xr0 = x + (size_t)r0c * EMBED;
        const float* xr8 = x + (size_t)r8c * EMBED;

        // Hoist all A fragments: a[kt][0..3], packed half2.
        unsigned int a[4][4];
        #pragma unroll
        for (int kt = 0; kt < 4; kt++) {
            int k0 = kt * 16;
            float2 p00 = *(const float2*)(xr0 + k0 + 2 * tig);
            float2 p80 = *(const float2*)(xr8 + k0 + 2 * tig);
            float2 p08 = *(const float2*)(xr0 + k0 + 2 * tig + 8);
            float2 p88 = *(const float2*)(xr8 + k0 + 2 * tig + 8);
            a[kt][0] = pack_h2(p00.x, p00.y);
            a[kt][1] = pack_h2(p80.x, p80.y);
            a[kt][2] = pack_h2(p08.x, p08.y);
            a[kt][3] = pack_h2(p88.x, p88.y);
        }

        float c[8][4];
        #pragma unroll
        for (int nt = 0; nt < 8; nt++)
            c[nt][0] = c[nt][1] = c[nt][2] = c[nt][3] = 0.f;

        #pragma unroll
        for (int kt = 0; kt < 4; kt++) {
            #pragma unroll
            for (int nt = 0; nt < 8; nt++) {
                // B fragment (k16n8 col-major): B[k][n] = W[n][k], n = nt*8+g
                const unsigned int* wrow = wp + (nt * 8 + g) * WPSTRIDE + 8 * kt + tig;
                unsigned int b0 = wrow[0];
                unsigned int b1 = wrow[4];
                asm volatile(
                    "mma.sync.aligned.m16n8k16.row.col.f32.f16.f16.f32 "
                    "{%0,%1,%2,%3}, {%4,%5,%6,%7}, {%8,%9}, {%0,%1,%2,%3};"
                    : "+f"(c[nt][0]), "+f"(c[nt][1]), "+f"(c[nt][2]), "+f"(c[nt][3])
                    : "r"(a[kt][0]), "r"(a[kt][1]), "r"(a[kt][2]), "r"(a[kt][3]),
                      "r"(b0), "r"(b1));
            }
        }

        // Epilogue: bias + relu + fp16 pack.
        unsigned int* hp = (unsigned int*)g_h;  // 2 halves per u32
        #pragma unroll
        for (int nt = 0; nt < 8; nt++) {
            int col = nt * 8 + 2 * tig;
            float b0v = bs[col], b1v = bs[col + 1];
            unsigned int h0 = pack_h2(fmaxf(c[nt][0] + b0v, 0.f),
                                      fmaxf(c[nt][1] + b1v, 0.f));
            unsigned int h1 = pack_h2(fmaxf(c[nt][2] + b0v, 0.f),
                                      fmaxf(c[nt][3] + b1v, 0.f));
            if (row0 < n_nodes)
                hp[((size_t)row0 * EMBED + col) >> 1] = h0;
            if (row8 < n_nodes)
                hp[((size_t)row8 * EMBED + col) >> 1] = h1;
        }
    }
}

// ---------------------------------------------------------------------------
// Kernel 2: chain build. Edge e pushes onto parity chain head[4*src + (e&3)]
// and records {next, tgt} at g_link[e] (coalesced store). 4 edges per thread
// (quad-aligned: parities are exactly 0,1,2,3).
// ---------------------------------------------------------------------------
__global__ void __launch_bounds__(256) chain_kernel(const void* __restrict__ ei_raw,
                                                    int n_edges)
{
    __shared__ int s_is64;
    if (threadIdx.x == 0) s_is64 = sniff_is64(ei_raw);
    __syncthreads();
    int is64 = s_is64;

    int p = blockIdx.x * 256 + threadIdx.x;   // quad index
    int nq = n_edges >> 2;
    if (p < nq) {
        int e = p * 4;
        int s0, s1, s2, s3, t0, t1, t2, t3;
        if (is64) {
            const ulonglong2* ei2 = (const ulonglong2*)ei_raw;
            size_t tb = (size_t)(n_edges >> 1);
            ulonglong2 sa = ei2[2 * p],      sb  = ei2[2 * p + 1];
            ulonglong2 ta = ei2[tb + 2 * p], tbv = ei2[tb + 2 * p + 1];
            s0 = (int)sa.x; s1 = (int)sa.y; s2 = (int)sb.x; s3 = (int)sb.y;
            t0 = (int)ta.x; t1 = (int)ta.y; t2 = (int)tbv.x; t3 = (int)tbv.y;
        } else {
            const int4* ei4 = (const int4*)ei_raw;
            size_t tb = (size_t)(n_edges >> 2);
            int4 sv = ei4[p];
            int4 tv = ei4[tb + p];
            s0 = sv.x; s1 = sv.y; s2 = sv.z; s3 = sv.w;
            t0 = tv.x; t1 = tv.y; t2 = tv.z; t3 = tv.w;
        }
        int o0 = atomicExch(&g_head[4 * s0],     e + 1);
        int o1 = atomicExch(&g_head[4 * s1 + 1], e + 2);
        int o2 = atomicExch(&g_head[4 * s2 + 2], e + 3);
        int o3 = atomicExch(&g_head[4 * s3 + 3], e + 4);
        g_link[e]     = make_int2(o0, t0);
        g_link[e + 1] = make_int2(o1, t1);
        g_link[e + 2] = make_int2(o2, t2);
        g_link[e + 3] = make_int2(o3, t3);
    } else if (p == nq) {
        for (int e = p * 4; e < n_edges; e++) {
            int src, tgt;
            if (is64) {
                const long long* ei = (const long long*)ei_raw;
                src = (int)ei[e];
                tgt = (int)ei[(size_t)n_edges + e];
            } else {
                const int* ei = (const int*)ei_raw;
                src = ei[e];
                tgt = ei[(size_t)n_edges + e];
            }
            int o = atomicExch(&g_head[4 * src + (e & 3)], e + 1);
            g_link[e] = make_int2(o, tgt);
        }
    }
}

// ---------------------------------------------------------------------------
// Kernel 3: chain-walk gather-reduce + mean. 8 lanes per node; lane j owns
// 16B (8 fp16) of the 128B row. Four parity chains walked with independent
// cursors (4 link + up to 4 row loads in flight). Heads loaded/reset as one
// int4. Resets heads for the next graph replay.
// ---------------------------------------------------------------------------
__global__ void __launch_bounds__(256) accumulate_kernel(float4* __restrict__ out4,
                                                         int n_nodes)
{
    int t = blockIdx.x * 256 + threadIdx.x;
    int n = t >> 3;
    int j = t & 7;
    if (n >= n_nodes) return;

    int4 hd = *(const int4*)&g_head[4 * n];
    int cur[4] = {hd.x, hd.y, hd.z, hd.w};

    const uint4* hp = (const uint4*)g_h;   // row = 8 uint4
    float acc[8] = {0.f, 0.f, 0.f, 0.f, 0.f, 0.f, 0.f, 0.f};
    int deg = 0;

    while (cur[0] | cur[1] | cur[2] | cur[3]) {
        int2 ln[4];
        #pragma unroll
        for (int q = 0; q < 4; q++)
            if (cur[q]) ln[q] = __ldg(&g_link[cur[q] - 1]);
        #pragma unroll
        for (int q = 0; q < 4; q++) {
            if (cur[q]) {
                uint4 v = hp[(size_t)ln[q].y * 8 + j];
                cur[q] = ln[q].x;
                deg++;
                #pragma unroll
                for (int w = 0; w < 4; w++) {
                    unsigned int u = (&v.x)[w];
                    float2 f = __half22float2(*(__half2*)&u);
                    acc[2 * w]     += f.x;
                    acc[2 * w + 1] += f.y;
                }
            }
        }
    }

    if (j == 0)   // restore invariant for next replay
        *(int4*)&g_head[4 * n] = make_int4(0, 0, 0, 0);

    float inv = 1.0f / fmaxf((float)deg, 1.0f);
    size_t base = (size_t)n * 16 + 2 * j;   // lane j owns floats [8j, 8j+8)
    out4[base]     = make_float4(acc[0] * inv, acc[1] * inv, acc[2] * inv, acc[3] * inv);
    out4[base + 1] = make_float4(acc[4] * inv, acc[5] * inv, acc[6] * inv, acc[7] * inv);
}

// ---------------------------------------------------------------------------
// Launch: gemm forked to a side stream; chain build on main stream; join
// before the chain-walk accumulate.
// ---------------------------------------------------------------------------
extern "C" void kernel_launch(void* const* d_in, const int* in_sizes, int n_in,
                              void* d_out, int out_size)
{
    const float* x  = (const float*)d_in[0];
    const void*  ei = d_in[1];
    const float* W  = (const float*)d_in[2];
    const float* b  = (const float*)d_in[3];
    float*       out = (float*)d_out;

    int N  = in_sizes[0] / EMBED;          // 100000
    int E  = in_sizes[1] / 2;              // 1600000
    int EQ = E / 4 + 1;                    // edge quads (+1 tail thread)
    int GB = 296;                          // 2 blocks/SM, one full wave

    cudaStream_t s2;
    cudaEvent_t evFork, evJoin;
    cudaStreamCreateWithFlags(&s2, cudaStreamNonBlocking);
    cudaEventCreateWithFlags(&evFork, cudaEventDisableTiming);
    cudaEventCreateWithFlags(&evJoin, cudaEventDisableTiming);

    // Fork: gemm on side stream.
    cudaEventRecord(evFork, 0);
    cudaStreamWaitEvent(s2, evFork, 0);
    gemm_relu_kernel<<<GB, 256, 0, s2>>>(x, W, b, N);
    cudaEventRecord(evJoin, s2);

    // Main stream: build per-src parity chains.
    chain_kernel<<<(EQ + 255) / 256, 256>>>(ei, E);

    // Join, then walk the chains.
    cudaStreamWaitEvent(0, evJoin, 0);
    long long at = (long long)N * 8;
    accumulate_kernel<<<(int)((at + 255) / 256), 256>>>((float4*)out, N);
}

// round 16
// speedup vs baseline: 1.5843x; 1.1766x over previous
#include <cuda_runtime.h>
#include <cuda_fp16.h>

#define EMBED 64
#define MAX_NODES 100000
#define MAX_EDGES 1600000
#define NSLOT 32
#define WPSTRIDE 36   // smem stride (u32) for packed W -> bank = 4g+tig, conflict-free

// Scratch (zero-initialized at module load; accumulate re-zeroes g_cnt/g_head
// each run so graph replays always start from a clean state).
__device__ __half g_h[(size_t)MAX_NODES * EMBED];   // relu(x@W^T+b), fp16
__device__ int    g_cnt[MAX_NODES];                 // per-node edge count (reset by accumulate)
__device__ int    g_slots[(size_t)MAX_NODES * NSLOT]; // first 32 tgt per node
__device__ int    g_head[MAX_NODES];                // overflow chain head; 0=empty
__device__ int2   g_link[MAX_EDGES];                // overflow links {next, tgt}

// Per-block inline dtype sniff: int64 edge data with node ids < 1e5 has zero
// high halves; int32 data packs two random ids per u64 word.
__device__ __forceinline__ int sniff_is64(const void* ei_raw) {
    const unsigned long long* e8 = (const unsigned long long*)ei_raw;
    int ok64 = 1;
    #pragma unroll
    for (int k = 0; k < 8; k++) {
        unsigned long long v = e8[k];
        if ((v >> 32) != 0ull || (v & 0xffffffffull) >= (1u << 28)) ok64 = 0;
    }
    return ok64;
}

__device__ __forceinline__ unsigned int pack_h2(float lo, float hi) {
    __half2 h = __floats2half2_rn(lo, hi);
    return *(unsigned int*)&h;
}

// ---------------------------------------------------------------------------
// Kernel 1: h = relu(x @ W^T + b) via mma.sync.m16n8k16.f16 (f32 accum).
// Grid-stride over 16-node tiles, W staged once per block; 16 hoisted A
// loads (MLP=16), 32 MMA/tile, conflict-free smem B reads.
// ---------------------------------------------------------------------------
__global__ void __launch_bounds__(256) gemm_relu_kernel(
    const float* __restrict__ x,
    const float* __restrict__ W,
    const float* __restrict__ b,
    int n_nodes)
{
    __shared__ unsigned int wp[EMBED * WPSTRIDE];  // wp[o][kk] = half2(W[o][2kk], W[o][2kk+1])
    __shared__ float bs[EMBED];

    int tid = threadIdx.x;
    for (int i = tid; i < EMBED * 32; i += 256) {
        int o = i >> 5, kk = i & 31;
        const float2 v = *(const float2*)(W + o * EMBED + 2 * kk);
        wp[o * WPSTRIDE + kk] = pack_h2(v.x, v.y);
    }
    if (tid < EMBED) bs[tid] = b[tid];
    __syncthreads();

    int lane = tid & 31;
    int g   = lane >> 2;   // group 0..7
    int tig = lane & 3;    // 0..3

    int warp0  = (blockIdx.x * 256 + tid) >> 5;
    int nwarps = (gridDim.x * 256) >> 5;
    int ntiles = (n_nodes + 15) >> 4;

    for (int tile = warp0; tile < ntiles; tile += nwarps) {
        int m0 = tile * 16;
        int row0 = m0 + g;
        int row8 = m0 + g + 8;
        int r0c = (row0 < n_nodes) ? row0 : (n_nodes - 1);
        int r8c = (row8 < n_nodes) ? row8 : (n_nodes - 1);
        const float* xr0 = x + (size_t)r0c * EMBED;
        const float* xr8 = x + (size_t)r8c * EMBED;

        unsigned int a[4][4];
        #pragma unroll
        for (int kt = 0; kt < 4; kt++) {
            int k0 = kt * 16;
            float2 p00 = *(const float2*)(xr0 + k0 + 2 * tig);
            float2 p80 = *(const float2*)(xr8 + k0 + 2 * tig);
            float2 p08 = *(const float2*)(xr0 + k0 + 2 * tig + 8);
            float2 p88 = *(const float2*)(xr8 + k0 + 2 * tig + 8);
            a[kt][0] = pack_h2(p00.x, p00.y);
            a[kt][1] = pack_h2(p80.x, p80.y);
            a[kt][2] = pack_h2(p08.x, p08.y);
            a[kt][3] = pack_h2(p88.x, p88.y);
        }

        float c[8][4];
        #pragma unroll
        for (int nt = 0; nt < 8; nt++)
            c[nt][0] = c[nt][1] = c[nt][2] = c[nt][3] = 0.f;

        #pragma unroll
        for (int kt = 0; kt < 4; kt++) {
            #pragma unroll
            for (int nt = 0; nt < 8; nt++) {
                const unsigned int* wrow = wp + (nt * 8 + g) * WPSTRIDE + 8 * kt + tig;
                unsigned int b0 = wrow[0];
                unsigned int b1 = wrow[4];
                asm volatile(
                    "mma.sync.aligned.m16n8k16.row.col.f32.f16.f16.f32 "
                    "{%0,%1,%2,%3}, {%4,%5,%6,%7}, {%8,%9}, {%0,%1,%2,%3};"
                    : "+f"(c[nt][0]), "+f"(c[nt][1]), "+f"(c[nt][2]), "+f"(c[nt][3])
                    : "r"(a[kt][0]), "r"(a[kt][1]), "r"(a[kt][2]), "r"(a[kt][3]),
                      "r"(b0), "r"(b1));
            }
        }

        unsigned int* hp = (unsigned int*)g_h;
        #pragma unroll
        for (int nt = 0; nt < 8; nt++) {
            int col = nt * 8 + 2 * tig;
            float b0v = bs[col], b1v = bs[col + 1];
            unsigned int h0 = pack_h2(fmaxf(c[nt][0] + b0v, 0.f),
                                      fmaxf(c[nt][1] + b1v, 0.f));
            unsigned int h1 = pack_h2(fmaxf(c[nt][2] + b0v, 0.f),
                                      fmaxf(c[nt][3] + b1v, 0.f));
            if (row0 < n_nodes)
                hp[((size_t)row0 * EMBED + col) >> 1] = h0;
            if (row8 < n_nodes)
                hp[((size_t)row8 * EMBED + col) >> 1] = h1;
        }
    }
}

// ---------------------------------------------------------------------------
// Kernel 2: bucket build. Edge e: pos = atomicAdd(cnt[src]); pos < 32 goes
// into the flat slot array, overflow edges push onto a per-node chain.
// 4 edges per thread, vectorized loads.
// ---------------------------------------------------------------------------
__device__ __forceinline__ void push_edge(int src, int tgt, int e) {
    int pos = atomicAdd(&g_cnt[src], 1);
    if (pos < NSLOT) {
        g_slots[(size_t)src * NSLOT + pos] = tgt;
    } else {
        int o = atomicExch(&g_head[src], e + 1);
        g_link[e] = make_int2(o, tgt);
    }
}

__global__ void __launch_bounds__(256) build_kernel(const void* __restrict__ ei_raw,
                                                    int n_edges)
{
    __shared__ int s_is64;
    if (threadIdx.x == 0) s_is64 = sniff_is64(ei_raw);
    __syncthreads();
    int is64 = s_is64;

    int p = blockIdx.x * 256 + threadIdx.x;   // quad index
    int nq = n_edges >> 2;
    if (p < nq) {
        int e = p * 4;
        int s0, s1, s2, s3, t0, t1, t2, t3;
        if (is64) {
            const ulonglong2* ei2 = (const ulonglong2*)ei_raw;
            size_t tb = (size_t)(n_edges >> 1);
            ulonglong2 sa = ei2[2 * p],      sb  = ei2[2 * p + 1];
            ulonglong2 ta = ei2[tb + 2 * p], tbv = ei2[tb + 2 * p + 1];
            s0 = (int)sa.x; s1 = (int)sa.y; s2 = (int)sb.x; s3 = (int)sb.y;
            t0 = (int)ta.x; t1 = (int)ta.y; t2 = (int)tbv.x; t3 = (int)tbv.y;
        } else {
            const int4* ei4 = (const int4*)ei_raw;
            size_t tb = (size_t)(n_edges >> 2);
            int4 sv = ei4[p];
            int4 tv = ei4[tb + p];
            s0 = sv.x; s1 = sv.y; s2 = sv.z; s3 = sv.w;
            t0 = tv.x; t1 = tv.y; t2 = tv.z; t3 = tv.w;
        }
        push_edge(s0, t0, e);
        push_edge(s1, t1, e + 1);
        push_edge(s2, t2, e + 2);
        push_edge(s3, t3, e + 3);
    } else if (p == nq) {
        for (int e = p * 4; e < n_edges; e++) {
            int src, tgt;
            if (is64) {
                const long long* ei = (const long long*)ei_raw;
                src = (int)ei[e];
                tgt = (int)ei[(size_t)n_edges + e];
            } else {
                const int* ei = (const int*)ei_raw;
                src = ei[e];
                tgt = ei[(size_t)n_edges + e];
            }
            push_edge(src, tgt, e);
        }
    }
}

// ---------------------------------------------------------------------------
// Kernel 3: bucket gather-reduce + mean. 8 lanes per node; lane j owns 16B
// (8 fp16) of the 128B row. Indices read as int4 broadcasts (no chasing);
// row gathers are independent 128B lines -> high MLP. Rare overflow chain
// walked after the flat slots. Resets cnt/head for the next graph replay.
// ---------------------------------------------------------------------------
__global__ void __launch_bounds__(256) accumulate_kernel(float4* __restrict__ out4,
                                                         int n_nodes)
{
    int t = blockIdx.x * 256 + threadIdx.x;
    int n = t >> 3;
    int j = t & 7;
    if (n >= n_nodes) return;

    int deg   = g_cnt[n];
    int nflat = (deg < NSLOT) ? deg : NSLOT;
    const int* slots = g_slots + (size_t)n * NSLOT;

    const uint4* hp = (const uint4*)g_h;   // row = 8 uint4
    float acc[8] = {0.f, 0.f, 0.f, 0.f, 0.f, 0.f, 0.f, 0.f};

    int k = 0;
    for (; k + 4 <= nflat; k += 4) {
        int4 q = *(const int4*)(slots + k);
        uint4 v0 = hp[(size_t)q.x * 8 + j];
        uint4 v1 = hp[(size_t)q.y * 8 + j];
        uint4 v2 = hp[(size_t)q.z * 8 + j];
        uint4 v3 = hp[(size_t)q.w * 8 + j];
        #pragma unroll
        for (int w = 0; w < 4; w++) {
            unsigned int u0 = (&v0.x)[w];
            unsigned int u1 = (&v1.x)[w];
            unsigned int u2 = (&v2.x)[w];
            unsigned int u3 = (&v3.x)[w];
            float2 f0 = __half22float2(*(__half2*)&u0);
            float2 f1 = __half22float2(*(__half2*)&u1);
            float2 f2 = __half22float2(*(__half2*)&u2);
            float2 f3 = __half22float2(*(__half2*)&u3);
            acc[2 * w]     += (f0.x + f1.x) + (f2.x + f3.x);
            acc[2 * w + 1] += (f0.y + f1.y) + (f2.y + f3.y);
        }
    }
    if (k < nflat) {
        int4 q = *(const int4*)(slots + k);   // within the 32-slot region, safe
        int idx[4] = {q.x, q.y, q.z, q.w};
        #pragma unroll
        for (int i = 0; i < 4; i++) {
            if (k + i < nflat) {
                uint4 v = hp[(size_t)idx[i] * 8 + j];
                #pragma unroll
                for (int w = 0; w < 4; w++) {
                    unsigned int u = (&v.x)[w];
                    float2 f = __half22float2(*(__half2*)&u);
                    acc[2 * w]     += f.x;
                    acc[2 * w + 1] += f.y;
                }
            }
        }
    }

    // Rare overflow (deg > 32): walk the chain.
    if (deg > NSLOT) {
        int e1 = g_head[n];
        while (e1) {
            int2 ln = __ldg(&g_link[e1 - 1]);
            uint4 v = hp[(size_t)ln.y * 8 + j];
            e1 = ln.x;
            #pragma unroll
            for (int w = 0; w < 4; w++) {
                unsigned int u = (&v.x)[w];
                float2 f = __half22float2(*(__half2*)&u);
                acc[2 * w]     += f.x;
                acc[2 * w + 1] += f.y;
            }
        }
    }

    if (j == 0) {   // restore invariant for next replay
        g_cnt[n]  = 0;
        g_head[n] = 0;
    }

    float inv = 1.0f / fmaxf((float)deg, 1.0f);
    size_t base = (size_t)n * 16 + 2 * j;   // lane j owns floats [8j, 8j+8)
    out4[base]     = make_float4(acc[0] * inv, acc[1] * inv, acc[2] * inv, acc[3] * inv);
    out4[base + 1] = make_float4(acc[4] * inv, acc[5] * inv, acc[6] * inv, acc[7] * inv);
}

// ---------------------------------------------------------------------------
// Launch: gemm forked to a side stream; bucket build on main stream; join
// before the gather-reduce.
// ---------------------------------------------------------------------------
extern "C" void kernel_launch(void* const* d_in, const int* in_sizes, int n_in,
                              void* d_out, int out_size)
{
    const float* x  = (const float*)d_in[0];
    const void*  ei = d_in[1];
    const float* W  = (const float*)d_in[2];
    const float* b  = (const float*)d_in[3];
    float*       out = (float*)d_out;

    int N  = in_sizes[0] / EMBED;          // 100000
    int E  = in_sizes[1] / 2;              // 1600000
    int EQ = E / 4 + 1;                    // edge quads (+1 tail thread)
    int GB = 296;                          // 2 blocks/SM

    cudaStream_t s2;
    cudaEvent_t evFork, evJoin;
    cudaStreamCreateWithFlags(&s2, cudaStreamNonBlocking);
    cudaEventCreateWithFlags(&evFork, cudaEventDisableTiming);
    cudaEventCreateWithFlags(&evJoin, cudaEventDisableTiming);

    // Fork: gemm on side stream.
    cudaEventRecord(evFork, 0);
    cudaStreamWaitEvent(s2, evFork, 0);
    gemm_relu_kernel<<<GB, 256, 0, s2>>>(x, W, b, N);
    cudaEventRecord(evJoin, s2);

    // Main stream: fill per-src slot buckets.
    build_kernel<<<(EQ + 255) / 256, 256>>>(ei, E);

    // Join, then gather-reduce.
    cudaStreamWaitEvent(0, evJoin, 0);
    long long at = (long long)N * 8;
    accumulate_kernel<<<(int)((at + 255) / 256), 256>>>((float4*)out, N);
}